// round 1
// baseline (speedup 1.0000x reference)
#include <cuda_runtime.h>
#include <math.h>

#define T_DIM 64
#define B_DIM 512
#define D_DIM 768
#define H_DIM 12
#define HD_DIM 64
#define D3 (3 * D_DIM)

// Scratch (allocation-free rule: __device__ globals)
__device__ float g_qkv[(long long)T_DIM * B_DIM * D3];     // 302 MB
__device__ float g_ctx[(long long)T_DIM * B_DIM * D_DIM];  // 100 MB
__device__ float g_out[(long long)T_DIM * B_DIM * D_DIM];  // 100 MB
__device__ float g_inv[T_DIM * B_DIM];
__device__ float g_mean[T_DIM * D_DIM];

// ---------------------------------------------------------------------------
// SGEMM (NT): C[M,N] = A[M,K] * B[N,K]^T + bias[N]
// 128x128 tile, BK=8, 256 threads, 8x8 micro-tile per thread.
// All dims are multiples of tile sizes for this problem -> no bounds checks.
// ---------------------------------------------------------------------------
__global__ __launch_bounds__(256) void sgemm_nt_bias(
    const float* __restrict__ A, const float* __restrict__ Bm,
    const float* __restrict__ bias, float* __restrict__ C,
    int M, int N, int K)
{
    __shared__ float As[8][132];
    __shared__ float Bs[8][132];
    const int tid = threadIdx.x;
    const int ty = tid >> 4, tx = tid & 15;
    const int bm = blockIdx.y * 128, bn = blockIdx.x * 128;
    const int lr = tid >> 1;
    const int lc = (tid & 1) << 2;
    const float* Ag = A + (size_t)(bm + lr) * K + lc;
    const float* Bg = Bm + (size_t)(bn + lr) * K + lc;

    float acc[8][8];
#pragma unroll
    for (int i = 0; i < 8; i++)
#pragma unroll
        for (int j = 0; j < 8; j++) acc[i][j] = 0.f;

    for (int k0 = 0; k0 < K; k0 += 8) {
        float4 av = *(const float4*)(Ag + k0);
        float4 bv = *(const float4*)(Bg + k0);
        As[lc + 0][lr] = av.x; As[lc + 1][lr] = av.y;
        As[lc + 2][lr] = av.z; As[lc + 3][lr] = av.w;
        Bs[lc + 0][lr] = bv.x; Bs[lc + 1][lr] = bv.y;
        Bs[lc + 2][lr] = bv.z; Bs[lc + 3][lr] = bv.w;
        __syncthreads();
#pragma unroll
        for (int k = 0; k < 8; k++) {
            float a[8], b[8];
            *(float4*)(a)     = *(const float4*)&As[k][ty * 4];
            *(float4*)(a + 4) = *(const float4*)&As[k][64 + ty * 4];
            *(float4*)(b)     = *(const float4*)&Bs[k][tx * 4];
            *(float4*)(b + 4) = *(const float4*)&Bs[k][64 + tx * 4];
#pragma unroll
            for (int i = 0; i < 8; i++)
#pragma unroll
                for (int j = 0; j < 8; j++)
                    acc[i][j] = fmaf(a[i], b[j], acc[i][j]);
        }
        __syncthreads();
    }

#pragma unroll
    for (int ih = 0; ih < 2; ih++)
#pragma unroll
        for (int i = 0; i < 4; i++) {
            int r = bm + ih * 64 + ty * 4 + i;
#pragma unroll
            for (int jh = 0; jh < 2; jh++) {
                int c = bn + jh * 64 + tx * 4;
                float4 o;
                o.x = acc[ih * 4 + i][jh * 4 + 0] + bias[c + 0];
                o.y = acc[ih * 4 + i][jh * 4 + 1] + bias[c + 1];
                o.z = acc[ih * 4 + i][jh * 4 + 2] + bias[c + 2];
                o.w = acc[ih * 4 + i][jh * 4 + 3] + bias[c + 3];
                *(float4*)(C + (size_t)r * N + c) = o;
            }
        }
}

// ---------------------------------------------------------------------------
// Flash-style attention, one (t, h, 64-query-tile) per block, 256 threads.
// Q scaled by 1/sqrt(64) at load. Online softmax. K/V streamed in 64-row tiles.
// ---------------------------------------------------------------------------
#define AST 68   // smem row stride (floats), keeps float4 alignment

__global__ __launch_bounds__(256) void attn_kernel(
    const float* __restrict__ qkv, float* __restrict__ ctx)
{
    extern __shared__ float sm[];
    float (*Qs)[AST] = (float(*)[AST])(sm);                 // [d][q]
    float (*Ks)[AST] = (float(*)[AST])(sm + 64 * AST);      // [d][k]
    float (*Vs)[AST] = (float(*)[AST])(sm + 2 * 64 * AST);  // [k][d]
    float (*Ps)[AST] = (float(*)[AST])(sm + 3 * 64 * AST);  // [k][q]

    const int tid = threadIdx.x;
    const int ty = tid >> 4, tx = tid & 15;
    const int q0 = blockIdx.x * 64;
    const int h  = blockIdx.y;
    const int t  = blockIdx.z;
    const size_t base = (size_t)t * B_DIM * D3;
    const int lr = tid >> 2;
    const int dc = (tid & 3) << 4;

    // Load Q tile transposed + pre-scaled
    {
        const float* src = qkv + base + (size_t)(q0 + lr) * D3 + h * HD_DIM + dc;
#pragma unroll
        for (int j = 0; j < 16; j += 4) {
            float4 v = *(const float4*)(src + j);
            Qs[dc + j + 0][lr] = v.x * 0.125f;
            Qs[dc + j + 1][lr] = v.y * 0.125f;
            Qs[dc + j + 2][lr] = v.z * 0.125f;
            Qs[dc + j + 3][lr] = v.w * 0.125f;
        }
    }

    float m[4], l[4], O[4][4];
#pragma unroll
    for (int i = 0; i < 4; i++) {
        m[i] = -INFINITY; l[i] = 0.f;
#pragma unroll
        for (int j = 0; j < 4; j++) O[i][j] = 0.f;
    }

    for (int kt = 0; kt < B_DIM / 64; ++kt) {
        __syncthreads();
        {
            const float* ks = qkv + base + (size_t)(kt * 64 + lr) * D3 + D_DIM + h * HD_DIM + dc;
            const float* vs = ks + D_DIM;
#pragma unroll
            for (int j = 0; j < 16; j += 4) {
                float4 kv = *(const float4*)(ks + j);
                Ks[dc + j + 0][lr] = kv.x; Ks[dc + j + 1][lr] = kv.y;
                Ks[dc + j + 2][lr] = kv.z; Ks[dc + j + 3][lr] = kv.w;
                float4 vv = *(const float4*)(vs + j);
                *(float4*)&Vs[lr][dc + j] = vv;
            }
        }
        __syncthreads();

        float S[4][4];
#pragma unroll
        for (int i = 0; i < 4; i++)
#pragma unroll
            for (int j = 0; j < 4; j++) S[i][j] = 0.f;

#pragma unroll
        for (int d = 0; d < 64; ++d) {
            float a[4], b[4];
            *(float4*)a = *(const float4*)&Qs[d][ty * 4];
            *(float4*)b = *(const float4*)&Ks[d][tx * 4];
#pragma unroll
            for (int i = 0; i < 4; i++)
#pragma unroll
                for (int j = 0; j < 4; j++)
                    S[i][j] = fmaf(a[i], b[j], S[i][j]);
        }

        // Online softmax over the 16 tx-lanes sharing each q-row
#pragma unroll
        for (int i = 0; i < 4; i++) {
            float mt = fmaxf(fmaxf(S[i][0], S[i][1]), fmaxf(S[i][2], S[i][3]));
#pragma unroll
            for (int o = 1; o < 16; o <<= 1)
                mt = fmaxf(mt, __shfl_xor_sync(0xffffffffu, mt, o));
            float mn = fmaxf(m[i], mt);
            float sc = __expf(m[i] - mn);
            float s = 0.f;
#pragma unroll
            for (int j = 0; j < 4; j++) {
                float p = __expf(S[i][j] - mn);
                Ps[tx * 4 + j][ty * 4 + i] = p;
                s += p;
            }
#pragma unroll
            for (int o = 1; o < 16; o <<= 1)
                s += __shfl_xor_sync(0xffffffffu, s, o);
            m[i] = mn;
            l[i] = l[i] * sc + s;
#pragma unroll
            for (int j = 0; j < 4; j++) O[i][j] *= sc;
        }
        __syncthreads();

#pragma unroll
        for (int k = 0; k < 64; ++k) {
            float p[4], v[4];
            *(float4*)p = *(const float4*)&Ps[k][ty * 4];
            *(float4*)v = *(const float4*)&Vs[k][tx * 4];
#pragma unroll
            for (int i = 0; i < 4; i++)
#pragma unroll
                for (int j = 0; j < 4; j++)
                    O[i][j] = fmaf(p[i], v[j], O[i][j]);
        }
    }

#pragma unroll
    for (int i = 0; i < 4; i++) {
        float inv = 1.f / l[i];
        int q = q0 + ty * 4 + i;
        float4 o;
        o.x = O[i][0] * inv; o.y = O[i][1] * inv;
        o.z = O[i][2] * inv; o.w = O[i][3] * inv;
        *(float4*)(ctx + ((size_t)t * B_DIM + q) * D_DIM + h * HD_DIM + tx * 4) = o;
    }
}

// ---------------------------------------------------------------------------
// Stage 4: adj[t,j] = (mean_i xn_i) . xn_j  (no BxB matrix!)
// ---------------------------------------------------------------------------
__global__ __launch_bounds__(256) void rownorm_kernel(
    const float* __restrict__ x, float* __restrict__ inv)
{
    int warp = threadIdx.x >> 5, lane = threadIdx.x & 31;
    int row = blockIdx.x * 8 + warp;
    const float* p = x + (size_t)row * D_DIM;
    float s = 0.f;
    for (int d = lane; d < D_DIM; d += 32) { float v = p[d]; s = fmaf(v, v, s); }
#pragma unroll
    for (int o = 16; o > 0; o >>= 1) s += __shfl_xor_sync(0xffffffffu, s, o);
    if (lane == 0) inv[row] = 1.f / fmaxf(sqrtf(s), 1e-8f);
}

__global__ __launch_bounds__(256) void mean_kernel(
    const float* __restrict__ x, const float* __restrict__ inv,
    float* __restrict__ mean)
{
    __shared__ float sinv[B_DIM];
    int t = blockIdx.x;
    int d = blockIdx.y * 256 + threadIdx.x;
    for (int i = threadIdx.x; i < B_DIM; i += 256) sinv[i] = inv[t * B_DIM + i];
    __syncthreads();
    const float* p = x + (size_t)t * B_DIM * D_DIM + d;
    float s = 0.f;
    for (int i = 0; i < B_DIM; i++) s = fmaf(p[(size_t)i * D_DIM], sinv[i], s);
    mean[t * D_DIM + d] = s * (1.f / B_DIM);
}

__global__ __launch_bounds__(256) void adj_kernel(
    const float* __restrict__ x, const float* __restrict__ inv,
    const float* __restrict__ mean, float* __restrict__ out)
{
    int warp = threadIdx.x >> 5, lane = threadIdx.x & 31;
    int row = blockIdx.x * 8 + warp;           // row = t*B + j
    int t = row >> 9;                           // /512
    const float* p = x + (size_t)row * D_DIM;
    const float* mp = mean + t * D_DIM;
    float s = 0.f;
    for (int d = lane; d < D_DIM; d += 32) s = fmaf(p[d], mp[d], s);
#pragma unroll
    for (int o = 16; o > 0; o >>= 1) s += __shfl_xor_sync(0xffffffffu, s, o);
    if (lane == 0) out[row] = s * inv[row];
}

// ---------------------------------------------------------------------------
extern "C" void kernel_launch(void* const* d_in, const int* in_sizes, int n_in,
                              void* d_out, int out_size)
{
    const float* node  = (const float*)d_in[0];
    const float* w_in  = (const float*)d_in[1];
    const float* b_in  = (const float*)d_in[2];
    const float* w_out = (const float*)d_in[3];
    const float* b_out = (const float*)d_in[4];
    float* out = (float*)d_out;

    float *qkv, *ctx, *o, *inv, *mean;
    cudaGetSymbolAddress((void**)&qkv,  g_qkv);
    cudaGetSymbolAddress((void**)&ctx,  g_ctx);
    cudaGetSymbolAddress((void**)&o,    g_out);
    cudaGetSymbolAddress((void**)&inv,  g_inv);
    cudaGetSymbolAddress((void**)&mean, g_mean);

    const int M = T_DIM * B_DIM;  // 32768
    const int attn_smem = 4 * 64 * AST * 4;  // 69632 bytes
    cudaFuncSetAttribute(attn_kernel,
                         cudaFuncAttributeMaxDynamicSharedMemorySize, attn_smem);

    // 1) QKV projection
    sgemm_nt_bias<<<dim3(D3 / 128, M / 128), 256>>>(node, w_in, b_in, qkv, M, D3, D_DIM);
    // 2) Attention (T*H*8 = 6144 blocks)
    attn_kernel<<<dim3(B_DIM / 64, H_DIM, T_DIM), 256, attn_smem>>>(qkv, ctx);
    // 3) Output projection
    sgemm_nt_bias<<<dim3(D_DIM / 128, M / 128), 256>>>(ctx, w_out, b_out, o, M, D_DIM, D_DIM);
    // 4) adjacency via mean-of-normalized-rows trick
    rownorm_kernel<<<M / 8, 256>>>(o, inv);
    mean_kernel<<<dim3(T_DIM, D_DIM / 256), 256>>>(o, inv, mean);
    adj_kernel<<<M / 8, 256>>>(o, inv, mean, out);
}

// round 5
// speedup vs baseline: 1.5516x; 1.5516x over previous
#include <cuda_runtime.h>
#include <cuda_bf16.h>
#include <math.h>
#include <stdint.h>

#define T_DIM 64
#define B_DIM 512
#define D_DIM 768
#define H_DIM 12
#define HD_DIM 64
#define D3 (3 * D_DIM)
#define M_DIM (T_DIM * B_DIM)   // 32768

// ---------------------------------------------------------------------------
// Scratch (allocation-free rule: __device__ globals)
// ---------------------------------------------------------------------------
__device__ float g_qkv[(size_t)M_DIM * D3];                 // 302 MB fp32
__device__ float g_out[(size_t)M_DIM * D_DIM];              // 100 MB fp32
__device__ __nv_bfloat16 g_nhi[(size_t)M_DIM * D_DIM];
__device__ __nv_bfloat16 g_nlo[(size_t)M_DIM * D_DIM];
__device__ __nv_bfloat16 g_chi[(size_t)M_DIM * D_DIM];
__device__ __nv_bfloat16 g_clo[(size_t)M_DIM * D_DIM];
__device__ __nv_bfloat16 g_wihi[(size_t)D3 * D_DIM];
__device__ __nv_bfloat16 g_wilo[(size_t)D3 * D_DIM];
__device__ __nv_bfloat16 g_wohi[(size_t)D_DIM * D_DIM];
__device__ __nv_bfloat16 g_wolo[(size_t)D_DIM * D_DIM];
__device__ float g_inv[M_DIM];
__device__ float g_mean[T_DIM * D_DIM];

// ---------------------------------------------------------------------------
// Portable PTX helpers (NO sm_103a-only instructions — harness compiles via
// compute_103, so tcgen05/TMEM are unavailable; mma.sync + cp.async are fine)
// ---------------------------------------------------------------------------
__device__ __forceinline__ void cpa16(uint32_t dst, const void* src) {
    asm volatile("cp.async.cg.shared.global [%0], [%1], 16;"
                 :: "r"(dst), "l"(src) : "memory");
}
__device__ __forceinline__ void cpa_commit() {
    asm volatile("cp.async.commit_group;" ::: "memory");
}
__device__ __forceinline__ void cpa_wait0() {
    asm volatile("cp.async.wait_group 0;" ::: "memory");
}

#define MMA16816(d, a, b)                                                   \
    asm volatile(                                                           \
        "mma.sync.aligned.m16n8k16.row.col.f32.bf16.bf16.f32 "             \
        "{%0,%1,%2,%3}, {%4,%5,%6,%7}, {%8,%9}, {%0,%1,%2,%3};"            \
        : "+f"((d)[0]), "+f"((d)[1]), "+f"((d)[2]), "+f"((d)[3])            \
        : "r"((a)[0]), "r"((a)[1]), "r"((a)[2]), "r"((a)[3]),               \
          "r"((b)[0]), "r"((b)[1]))

// ---------------------------------------------------------------------------
// fp32 -> bf16 hi/lo split (elementwise)
// ---------------------------------------------------------------------------
__device__ __forceinline__ void split2(float v, __nv_bfloat16& h, __nv_bfloat16& l) {
    h = __float2bfloat16(v);
    l = __float2bfloat16(v - __bfloat162float(h));
}

__global__ __launch_bounds__(256) void split_kernel(
    const float* __restrict__ x, __nv_bfloat16* __restrict__ hi,
    __nv_bfloat16* __restrict__ lo, int n)
{
    int i = (blockIdx.x * 256 + threadIdx.x) * 4;
    if (i >= n) return;
    float4 v = *(const float4*)(x + i);
    __nv_bfloat16 h0, h1, h2, h3, l0, l1, l2, l3;
    split2(v.x, h0, l0); split2(v.y, h1, l1);
    split2(v.z, h2, l2); split2(v.w, h3, l3);
    __nv_bfloat162 hh0; hh0.x = h0; hh0.y = h1;
    __nv_bfloat162 hh1; hh1.x = h2; hh1.y = h3;
    __nv_bfloat162 ll0; ll0.x = l0; ll0.y = l1;
    __nv_bfloat162 ll1; ll1.x = l2; ll1.y = l3;
    *(__nv_bfloat162*)(hi + i)     = hh0;
    *(__nv_bfloat162*)(hi + i + 2) = hh1;
    *(__nv_bfloat162*)(lo + i)     = ll0;
    *(__nv_bfloat162*)(lo + i + 2) = ll1;
}

// ---------------------------------------------------------------------------
// mma.sync split-bf16 GEMM (NT): C[M,N] = A[M,K]*B[N,K]^T + bias
//   C = Ahi*Bhi + Alo*Bhi + Ahi*Blo  (fp32 accumulate)
// 128x128 block, BK=32, 256 threads = 8 warps (2M x 4N), warp tile 64x32,
// cp.async double-buffered SMEM, pad-40 rows (conflict-free frag loads).
// ---------------------------------------------------------------------------
#define SA 40                         // smem row stride in halfs
#define TILE_H (128 * SA)             // halfs per tile (5120)
#define GEMM_SMEM (2 * 4 * TILE_H * 2)  // bytes: 2 stages x 4 tiles = 81920

__global__ __launch_bounds__(256) void gemm_mma(
    const __nv_bfloat16* __restrict__ Ahi, const __nv_bfloat16* __restrict__ Alo,
    const __nv_bfloat16* __restrict__ Bhi, const __nv_bfloat16* __restrict__ Blo,
    const float* __restrict__ bias, float* __restrict__ C, int N, int K)
{
    extern __shared__ __nv_bfloat16 sh[];
    const uint32_t sbase = (uint32_t)__cvta_generic_to_shared(sh);
    const int tid = threadIdx.x;
    const int wid = tid >> 5, lane = tid & 31;
    const int warp_m = wid >> 2, warp_n = wid & 3;
    const int bm = blockIdx.y * 128, bn = blockIdx.x * 128;

    // gmem->smem: each thread covers 32B (16 halfs) of one 128-row tile chunk
    const int lrow = tid >> 1;
    const int lofs = (tid & 1) * 16;          // halfs
    const __nv_bfloat16* srcs[4];
    srcs[0] = Ahi + (size_t)(bm + lrow) * K + lofs;
    srcs[1] = Alo + (size_t)(bm + lrow) * K + lofs;
    srcs[2] = Bhi + (size_t)(bn + lrow) * K + lofs;
    srcs[3] = Blo + (size_t)(bn + lrow) * K + lofs;
    const uint32_t sdst = sbase + (uint32_t)(lrow * SA + lofs) * 2;

    const int nchunks = K >> 5;               // K/32

    // preload chunk 0 into stage 0
#pragma unroll
    for (int tI = 0; tI < 4; tI++) {
        uint32_t d = sdst + tI * TILE_H * 2;
        cpa16(d, srcs[tI]);
        cpa16(d + 16, srcs[tI] + 8);
    }
    cpa_commit();

    float acc[4][4][4];
#pragma unroll
    for (int mi = 0; mi < 4; mi++)
#pragma unroll
        for (int ni = 0; ni < 4; ni++)
#pragma unroll
            for (int j = 0; j < 4; j++) acc[mi][ni][j] = 0.f;

    for (int c = 0; c < nchunks; ++c) {
        cpa_wait0();
        __syncthreads();

        if (c + 1 < nchunks) {
            const int s1 = (c + 1) & 1;
            const int ko = (c + 1) * 32;
#pragma unroll
            for (int tI = 0; tI < 4; tI++) {
                uint32_t d = sdst + (s1 * 4 + tI) * TILE_H * 2;
                cpa16(d, srcs[tI] + ko);
                cpa16(d + 16, srcs[tI] + ko + 8);
            }
            cpa_commit();
        }

        const __nv_bfloat16* sAhi = sh + ((c & 1) * 4 + 0) * TILE_H;
        const __nv_bfloat16* sAlo = sh + ((c & 1) * 4 + 1) * TILE_H;
        const __nv_bfloat16* sBhi = sh + ((c & 1) * 4 + 2) * TILE_H;
        const __nv_bfloat16* sBlo = sh + ((c & 1) * 4 + 3) * TILE_H;

#pragma unroll
        for (int ks = 0; ks < 2; ++ks) {
            const int k0 = ks * 16;
            const int rA = (lane >> 2);
            const int cA = k0 + (lane & 3) * 2;
            uint32_t ahi[4][4], alo[4][4];
#pragma unroll
            for (int mi = 0; mi < 4; mi++) {
                int r0 = warp_m * 64 + mi * 16 + rA;
                ahi[mi][0] = *(const uint32_t*)&sAhi[r0 * SA + cA];
                ahi[mi][1] = *(const uint32_t*)&sAhi[(r0 + 8) * SA + cA];
                ahi[mi][2] = *(const uint32_t*)&sAhi[r0 * SA + cA + 8];
                ahi[mi][3] = *(const uint32_t*)&sAhi[(r0 + 8) * SA + cA + 8];
                alo[mi][0] = *(const uint32_t*)&sAlo[r0 * SA + cA];
                alo[mi][1] = *(const uint32_t*)&sAlo[(r0 + 8) * SA + cA];
                alo[mi][2] = *(const uint32_t*)&sAlo[r0 * SA + cA + 8];
                alo[mi][3] = *(const uint32_t*)&sAlo[(r0 + 8) * SA + cA + 8];
            }
            uint32_t bhi[4][2], blo[4][2];
#pragma unroll
            for (int ni = 0; ni < 4; ni++) {
                int rn = warp_n * 32 + ni * 8 + rA;
                bhi[ni][0] = *(const uint32_t*)&sBhi[rn * SA + cA];
                bhi[ni][1] = *(const uint32_t*)&sBhi[rn * SA + cA + 8];
                blo[ni][0] = *(const uint32_t*)&sBlo[rn * SA + cA];
                blo[ni][1] = *(const uint32_t*)&sBlo[rn * SA + cA + 8];
            }
#pragma unroll
            for (int mi = 0; mi < 4; mi++)
#pragma unroll
                for (int ni = 0; ni < 4; ni++) {
                    MMA16816(acc[mi][ni], ahi[mi], bhi[ni]);
                    MMA16816(acc[mi][ni], alo[mi], bhi[ni]);
                    MMA16816(acc[mi][ni], ahi[mi], blo[ni]);
                }
        }
        __syncthreads();
    }

    // epilogue
#pragma unroll
    for (int mi = 0; mi < 4; mi++) {
        int row = bm + warp_m * 64 + mi * 16 + (lane >> 2);
#pragma unroll
        for (int ni = 0; ni < 4; ni++) {
            int col = bn + warp_n * 32 + ni * 8 + (lane & 3) * 2;
            float b0 = bias[col], b1 = bias[col + 1];
            float2 v0 = make_float2(acc[mi][ni][0] + b0, acc[mi][ni][1] + b1);
            float2 v1 = make_float2(acc[mi][ni][2] + b0, acc[mi][ni][3] + b1);
            *(float2*)(C + (size_t)row * N + col) = v0;
            *(float2*)(C + (size_t)(row + 8) * N + col) = v1;
        }
    }
}

// ---------------------------------------------------------------------------
// Flash-style attention (fp32 SIMT), writes ctx as bf16 hi/lo split directly.
// ---------------------------------------------------------------------------
#define AST 68

__global__ __launch_bounds__(256) void attn_kernel(
    const float* __restrict__ qkv, __nv_bfloat16* __restrict__ chi,
    __nv_bfloat16* __restrict__ clo)
{
    extern __shared__ float sm[];
    float (*Qs)[AST] = (float(*)[AST])(sm);
    float (*Ks)[AST] = (float(*)[AST])(sm + 64 * AST);
    float (*Vs)[AST] = (float(*)[AST])(sm + 2 * 64 * AST);
    float (*Ps)[AST] = (float(*)[AST])(sm + 3 * 64 * AST);

    const int tid = threadIdx.x;
    const int ty = tid >> 4, tx = tid & 15;
    const int q0 = blockIdx.x * 64;
    const int h  = blockIdx.y;
    const int t  = blockIdx.z;
    const size_t base = (size_t)t * B_DIM * D3;
    const int lr = tid >> 2;
    const int dc = (tid & 3) << 4;

    {
        const float* src = qkv + base + (size_t)(q0 + lr) * D3 + h * HD_DIM + dc;
#pragma unroll
        for (int j = 0; j < 16; j += 4) {
            float4 v = *(const float4*)(src + j);
            Qs[dc + j + 0][lr] = v.x * 0.125f;
            Qs[dc + j + 1][lr] = v.y * 0.125f;
            Qs[dc + j + 2][lr] = v.z * 0.125f;
            Qs[dc + j + 3][lr] = v.w * 0.125f;
        }
    }

    float m[4], l[4], O[4][4];
#pragma unroll
    for (int i = 0; i < 4; i++) {
        m[i] = -INFINITY; l[i] = 0.f;
#pragma unroll
        for (int j = 0; j < 4; j++) O[i][j] = 0.f;
    }

    for (int kt = 0; kt < B_DIM / 64; ++kt) {
        __syncthreads();
        {
            const float* ks = qkv + base + (size_t)(kt * 64 + lr) * D3 + D_DIM + h * HD_DIM + dc;
            const float* vs = ks + D_DIM;
#pragma unroll
            for (int j = 0; j < 16; j += 4) {
                float4 kv = *(const float4*)(ks + j);
                Ks[dc + j + 0][lr] = kv.x; Ks[dc + j + 1][lr] = kv.y;
                Ks[dc + j + 2][lr] = kv.z; Ks[dc + j + 3][lr] = kv.w;
                float4 vv = *(const float4*)(vs + j);
                *(float4*)&Vs[lr][dc + j] = vv;
            }
        }
        __syncthreads();

        float S[4][4];
#pragma unroll
        for (int i = 0; i < 4; i++)
#pragma unroll
            for (int j = 0; j < 4; j++) S[i][j] = 0.f;

#pragma unroll
        for (int d = 0; d < 64; ++d) {
            float a[4], b[4];
            *(float4*)a = *(const float4*)&Qs[d][ty * 4];
            *(float4*)b = *(const float4*)&Ks[d][tx * 4];
#pragma unroll
            for (int i = 0; i < 4; i++)
#pragma unroll
                for (int j = 0; j < 4; j++)
                    S[i][j] = fmaf(a[i], b[j], S[i][j]);
        }

#pragma unroll
        for (int i = 0; i < 4; i++) {
            float mt = fmaxf(fmaxf(S[i][0], S[i][1]), fmaxf(S[i][2], S[i][3]));
#pragma unroll
            for (int o = 1; o < 16; o <<= 1)
                mt = fmaxf(mt, __shfl_xor_sync(0xffffffffu, mt, o));
            float mn = fmaxf(m[i], mt);
            float sc = __expf(m[i] - mn);
            float s = 0.f;
#pragma unroll
            for (int j = 0; j < 4; j++) {
                float p = __expf(S[i][j] - mn);
                Ps[tx * 4 + j][ty * 4 + i] = p;
                s += p;
            }
#pragma unroll
            for (int o = 1; o < 16; o <<= 1)
                s += __shfl_xor_sync(0xffffffffu, s, o);
            m[i] = mn;
            l[i] = l[i] * sc + s;
#pragma unroll
            for (int j = 0; j < 4; j++) O[i][j] *= sc;
        }
        __syncthreads();

#pragma unroll
        for (int k = 0; k < 64; ++k) {
            float p[4], v[4];
            *(float4*)p = *(const float4*)&Ps[k][ty * 4];
            *(float4*)v = *(const float4*)&Vs[k][tx * 4];
#pragma unroll
            for (int i = 0; i < 4; i++)
#pragma unroll
                for (int j = 0; j < 4; j++)
                    O[i][j] = fmaf(p[i], v[j], O[i][j]);
        }
    }

#pragma unroll
    for (int i = 0; i < 4; i++) {
        float inv = 1.f / l[i];
        int q = q0 + ty * 4 + i;
        float o0 = O[i][0] * inv, o1 = O[i][1] * inv;
        float o2 = O[i][2] * inv, o3 = O[i][3] * inv;
        __nv_bfloat16 h0, h1, h2, h3, l0, l1, l2, l3;
        split2(o0, h0, l0); split2(o1, h1, l1);
        split2(o2, h2, l2); split2(o3, h3, l3);
        size_t idx = ((size_t)t * B_DIM + q) * D_DIM + h * HD_DIM + tx * 4;
        __nv_bfloat162 p0; p0.x = h0; p0.y = h1;
        __nv_bfloat162 p1; p1.x = h2; p1.y = h3;
        __nv_bfloat162 q0p; q0p.x = l0; q0p.y = l1;
        __nv_bfloat162 q1p; q1p.x = l2; q1p.y = l3;
        *(__nv_bfloat162*)(chi + idx)     = p0;
        *(__nv_bfloat162*)(chi + idx + 2) = p1;
        *(__nv_bfloat162*)(clo + idx)     = q0p;
        *(__nv_bfloat162*)(clo + idx + 2) = q1p;
    }
}

// ---------------------------------------------------------------------------
// Stage 4: adj[t,j] = (mean_i xn_i) . xn_j
// ---------------------------------------------------------------------------
__global__ __launch_bounds__(256) void rownorm_kernel(
    const float* __restrict__ x, float* __restrict__ inv)
{
    int warp = threadIdx.x >> 5, lane = threadIdx.x & 31;
    int row = blockIdx.x * 8 + warp;
    const float* p = x + (size_t)row * D_DIM;
    float s = 0.f;
    for (int d = lane; d < D_DIM; d += 32) { float v = p[d]; s = fmaf(v, v, s); }
#pragma unroll
    for (int o = 16; o > 0; o >>= 1) s += __shfl_xor_sync(0xffffffffu, s, o);
    if (lane == 0) inv[row] = 1.f / fmaxf(sqrtf(s), 1e-8f);
}

__global__ __launch_bounds__(256) void mean_kernel(
    const float* __restrict__ x, const float* __restrict__ inv,
    float* __restrict__ mean)
{
    __shared__ float sinv[B_DIM];
    int t = blockIdx.x;
    int d = blockIdx.y * 256 + threadIdx.x;
    for (int i = threadIdx.x; i < B_DIM; i += 256) sinv[i] = inv[t * B_DIM + i];
    __syncthreads();
    const float* p = x + (size_t)t * B_DIM * D_DIM + d;
    float s = 0.f;
    for (int i = 0; i < B_DIM; i++) s = fmaf(p[(size_t)i * D_DIM], sinv[i], s);
    mean[t * D_DIM + d] = s * (1.f / B_DIM);
}

__global__ __launch_bounds__(256) void adj_kernel(
    const float* __restrict__ x, const float* __restrict__ inv,
    const float* __restrict__ mean, float* __restrict__ out)
{
    int warp = threadIdx.x >> 5, lane = threadIdx.x & 31;
    int row = blockIdx.x * 8 + warp;
    int t = row >> 9;
    const float* p = x + (size_t)row * D_DIM;
    const float* mp = mean + t * D_DIM;
    float s = 0.f;
    for (int d = lane; d < D_DIM; d += 32) s = fmaf(p[d], mp[d], s);
#pragma unroll
    for (int o = 16; o > 0; o >>= 1) s += __shfl_xor_sync(0xffffffffu, s, o);
    if (lane == 0) out[row] = s * inv[row];
}

// ---------------------------------------------------------------------------
extern "C" void kernel_launch(void* const* d_in, const int* in_sizes, int n_in,
                              void* d_out, int out_size)
{
    const float* node  = (const float*)d_in[0];
    const float* w_in  = (const float*)d_in[1];
    const float* b_in  = (const float*)d_in[2];
    const float* w_out = (const float*)d_in[3];
    const float* b_out = (const float*)d_in[4];
    float* out = (float*)d_out;

    float *qkv, *o, *inv, *mean;
    __nv_bfloat16 *nhi, *nlo, *chi, *clo, *wihi, *wilo, *wohi, *wolo;
    cudaGetSymbolAddress((void**)&qkv,  g_qkv);
    cudaGetSymbolAddress((void**)&o,    g_out);
    cudaGetSymbolAddress((void**)&inv,  g_inv);
    cudaGetSymbolAddress((void**)&mean, g_mean);
    cudaGetSymbolAddress((void**)&nhi,  g_nhi);
    cudaGetSymbolAddress((void**)&nlo,  g_nlo);
    cudaGetSymbolAddress((void**)&chi,  g_chi);
    cudaGetSymbolAddress((void**)&clo,  g_clo);
    cudaGetSymbolAddress((void**)&wihi, g_wihi);
    cudaGetSymbolAddress((void**)&wilo, g_wilo);
    cudaGetSymbolAddress((void**)&wohi, g_wohi);
    cudaGetSymbolAddress((void**)&wolo, g_wolo);

    const int attn_smem = 4 * 64 * AST * 4;
    cudaFuncSetAttribute(attn_kernel,
                         cudaFuncAttributeMaxDynamicSharedMemorySize, attn_smem);
    cudaFuncSetAttribute(gemm_mma,
                         cudaFuncAttributeMaxDynamicSharedMemorySize, GEMM_SMEM);

    const int n_node = M_DIM * D_DIM;
    const int n_wi   = D3 * D_DIM;
    const int n_wo   = D_DIM * D_DIM;

    // 0) split fp32 -> bf16 hi/lo
    split_kernel<<<n_node / 1024, 256>>>(node, nhi, nlo, n_node);
    split_kernel<<<n_wi   / 1024, 256>>>(w_in, wihi, wilo, n_wi);
    split_kernel<<<n_wo   / 1024, 256>>>(w_out, wohi, wolo, n_wo);
    // 1) QKV projection (mma.sync split-bf16)
    gemm_mma<<<dim3(D3 / 128, M_DIM / 128), 256, GEMM_SMEM>>>(
        nhi, nlo, wihi, wilo, b_in, qkv, D3, D_DIM);
    // 2) Attention (writes ctx directly as bf16 hi/lo)
    attn_kernel<<<dim3(B_DIM / 64, H_DIM, T_DIM), 256, attn_smem>>>(qkv, chi, clo);
    // 3) Output projection
    gemm_mma<<<dim3(D_DIM / 128, M_DIM / 128), 256, GEMM_SMEM>>>(
        chi, clo, wohi, wolo, b_out, o, D_DIM, D_DIM);
    // 4) adjacency
    rownorm_kernel<<<M_DIM / 8, 256>>>(o, inv);
    mean_kernel<<<dim3(T_DIM, D_DIM / 256), 256>>>(o, inv, mean);
    adj_kernel<<<M_DIM / 8, 256>>>(o, inv, mean, out);
}

// round 10
// speedup vs baseline: 2.3812x; 1.5347x over previous
#include <cuda_runtime.h>
#include <cuda_bf16.h>
#include <math.h>
#include <stdint.h>

#define T_DIM 64
#define B_DIM 512
#define D_DIM 768
#define H_DIM 12
#define HD_DIM 64
#define D3 (3 * D_DIM)
#define M_DIM (T_DIM * B_DIM)   // 32768

// ---------------------------------------------------------------------------
// Scratch (allocation-free rule: __device__ globals)
// ---------------------------------------------------------------------------
__device__ float g_qkv[(size_t)M_DIM * D3];                 // 302 MB fp32
__device__ float g_out[(size_t)M_DIM * D_DIM];              // 100 MB fp32
__device__ __nv_bfloat16 g_nhi[(size_t)M_DIM * D_DIM];
__device__ __nv_bfloat16 g_nlo[(size_t)M_DIM * D_DIM];
__device__ __nv_bfloat16 g_chi[(size_t)M_DIM * D_DIM];
__device__ __nv_bfloat16 g_clo[(size_t)M_DIM * D_DIM];
__device__ __nv_bfloat16 g_wihi[(size_t)D3 * D_DIM];
__device__ __nv_bfloat16 g_wilo[(size_t)D3 * D_DIM];
__device__ __nv_bfloat16 g_wohi[(size_t)D_DIM * D_DIM];
__device__ __nv_bfloat16 g_wolo[(size_t)D_DIM * D_DIM];
__device__ float g_inv[M_DIM];
__device__ float g_mean[T_DIM * D_DIM];

// ---------------------------------------------------------------------------
// Portable PTX helpers (compute_103 virtual arch: mma.sync + cp.async only)
// ---------------------------------------------------------------------------
__device__ __forceinline__ void cpa16(uint32_t dst, const void* src) {
    asm volatile("cp.async.cg.shared.global [%0], [%1], 16;"
                 :: "r"(dst), "l"(src) : "memory");
}
__device__ __forceinline__ void cpa_commit() {
    asm volatile("cp.async.commit_group;" ::: "memory");
}
__device__ __forceinline__ void cpa_wait0() {
    asm volatile("cp.async.wait_group 0;" ::: "memory");
}

#define MMA16816(d, a, b)                                                   \
    asm volatile(                                                           \
        "mma.sync.aligned.m16n8k16.row.col.f32.bf16.bf16.f32 "             \
        "{%0,%1,%2,%3}, {%4,%5,%6,%7}, {%8,%9}, {%0,%1,%2,%3};"            \
        : "+f"((d)[0]), "+f"((d)[1]), "+f"((d)[2]), "+f"((d)[3])            \
        : "r"((a)[0]), "r"((a)[1]), "r"((a)[2]), "r"((a)[3]),               \
          "r"((b)[0]), "r"((b)[1]))

__device__ __forceinline__ void split2(float v, __nv_bfloat16& h, __nv_bfloat16& l) {
    h = __float2bfloat16(v);
    l = __float2bfloat16(v - __bfloat162float(h));
}
__device__ __forceinline__ uint32_t packbf(float a, float b) {
    __nv_bfloat162 t; t.x = __float2bfloat16(a); t.y = __float2bfloat16(b);
    return *(uint32_t*)&t;
}

// ---------------------------------------------------------------------------
// fp32 -> bf16 hi/lo split (elementwise)
// ---------------------------------------------------------------------------
__global__ __launch_bounds__(256) void split_kernel(
    const float* __restrict__ x, __nv_bfloat16* __restrict__ hi,
    __nv_bfloat16* __restrict__ lo, int n)
{
    int i = (blockIdx.x * 256 + threadIdx.x) * 4;
    if (i >= n) return;
    float4 v = *(const float4*)(x + i);
    __nv_bfloat16 h0, h1, h2, h3, l0, l1, l2, l3;
    split2(v.x, h0, l0); split2(v.y, h1, l1);
    split2(v.z, h2, l2); split2(v.w, h3, l3);
    __nv_bfloat162 hh0; hh0.x = h0; hh0.y = h1;
    __nv_bfloat162 hh1; hh1.x = h2; hh1.y = h3;
    __nv_bfloat162 ll0; ll0.x = l0; ll0.y = l1;
    __nv_bfloat162 ll1; ll1.x = l2; ll1.y = l3;
    *(__nv_bfloat162*)(hi + i)     = hh0;
    *(__nv_bfloat162*)(hi + i + 2) = hh1;
    *(__nv_bfloat162*)(lo + i)     = ll0;
    *(__nv_bfloat162*)(lo + i + 2) = ll1;
}

// ---------------------------------------------------------------------------
// mma.sync split-bf16 GEMM (NT): C = A*B^T + bias ; C = AhBh + AlBh + AhBl
// 128x128 block, BK=32, 8 warps (2Mx4N), cp.async double buffer.
// launch_bounds(256,2): cap regs at 128 so 2 CTAs/SM fit (occ was 12.4%).
// ---------------------------------------------------------------------------
#define SA 40
#define TILE_H (128 * SA)
#define GEMM_SMEM (2 * 4 * TILE_H * 2)

__global__ __launch_bounds__(256, 2) void gemm_mma(
    const __nv_bfloat16* __restrict__ Ahi, const __nv_bfloat16* __restrict__ Alo,
    const __nv_bfloat16* __restrict__ Bhi, const __nv_bfloat16* __restrict__ Blo,
    const float* __restrict__ bias, float* __restrict__ C, int N, int K)
{
    extern __shared__ __nv_bfloat16 sh[];
    const uint32_t sbase = (uint32_t)__cvta_generic_to_shared(sh);
    const int tid = threadIdx.x;
    const int wid = tid >> 5, lane = tid & 31;
    const int warp_m = wid >> 2, warp_n = wid & 3;
    const int bm = blockIdx.y * 128, bn = blockIdx.x * 128;

    const int lrow = tid >> 1;
    const int lofs = (tid & 1) * 16;
    const __nv_bfloat16* srcs[4];
    srcs[0] = Ahi + (size_t)(bm + lrow) * K + lofs;
    srcs[1] = Alo + (size_t)(bm + lrow) * K + lofs;
    srcs[2] = Bhi + (size_t)(bn + lrow) * K + lofs;
    srcs[3] = Blo + (size_t)(bn + lrow) * K + lofs;
    const uint32_t sdst = sbase + (uint32_t)(lrow * SA + lofs) * 2;

    const int nchunks = K >> 5;

#pragma unroll
    for (int tI = 0; tI < 4; tI++) {
        uint32_t d = sdst + tI * TILE_H * 2;
        cpa16(d, srcs[tI]);
        cpa16(d + 16, srcs[tI] + 8);
    }
    cpa_commit();

    float acc[4][4][4];
#pragma unroll
    for (int mi = 0; mi < 4; mi++)
#pragma unroll
        for (int ni = 0; ni < 4; ni++)
#pragma unroll
            for (int j = 0; j < 4; j++) acc[mi][ni][j] = 0.f;

    for (int c = 0; c < nchunks; ++c) {
        cpa_wait0();
        __syncthreads();

        if (c + 1 < nchunks) {
            const int s1 = (c + 1) & 1;
            const int ko = (c + 1) * 32;
#pragma unroll
            for (int tI = 0; tI < 4; tI++) {
                uint32_t d = sdst + (s1 * 4 + tI) * TILE_H * 2;
                cpa16(d, srcs[tI] + ko);
                cpa16(d + 16, srcs[tI] + ko + 8);
            }
            cpa_commit();
        }

        const __nv_bfloat16* sAhi = sh + ((c & 1) * 4 + 0) * TILE_H;
        const __nv_bfloat16* sAlo = sh + ((c & 1) * 4 + 1) * TILE_H;
        const __nv_bfloat16* sBhi = sh + ((c & 1) * 4 + 2) * TILE_H;
        const __nv_bfloat16* sBlo = sh + ((c & 1) * 4 + 3) * TILE_H;

#pragma unroll
        for (int ks = 0; ks < 2; ++ks) {
            const int k0 = ks * 16;
            const int rA = (lane >> 2);
            const int cA = k0 + (lane & 3) * 2;
            uint32_t ahi[4][4], alo[4][4];
#pragma unroll
            for (int mi = 0; mi < 4; mi++) {
                int r0 = warp_m * 64 + mi * 16 + rA;
                ahi[mi][0] = *(const uint32_t*)&sAhi[r0 * SA + cA];
                ahi[mi][1] = *(const uint32_t*)&sAhi[(r0 + 8) * SA + cA];
                ahi[mi][2] = *(const uint32_t*)&sAhi[r0 * SA + cA + 8];
                ahi[mi][3] = *(const uint32_t*)&sAhi[(r0 + 8) * SA + cA + 8];
                alo[mi][0] = *(const uint32_t*)&sAlo[r0 * SA + cA];
                alo[mi][1] = *(const uint32_t*)&sAlo[(r0 + 8) * SA + cA];
                alo[mi][2] = *(const uint32_t*)&sAlo[r0 * SA + cA + 8];
                alo[mi][3] = *(const uint32_t*)&sAlo[(r0 + 8) * SA + cA + 8];
            }
            uint32_t bhi[4][2], blo[4][2];
#pragma unroll
            for (int ni = 0; ni < 4; ni++) {
                int rn = warp_n * 32 + ni * 8 + rA;
                bhi[ni][0] = *(const uint32_t*)&sBhi[rn * SA + cA];
                bhi[ni][1] = *(const uint32_t*)&sBhi[rn * SA + cA + 8];
                blo[ni][0] = *(const uint32_t*)&sBlo[rn * SA + cA];
                blo[ni][1] = *(const uint32_t*)&sBlo[rn * SA + cA + 8];
            }
#pragma unroll
            for (int mi = 0; mi < 4; mi++)
#pragma unroll
                for (int ni = 0; ni < 4; ni++) {
                    MMA16816(acc[mi][ni], ahi[mi], bhi[ni]);
                    MMA16816(acc[mi][ni], alo[mi], bhi[ni]);
                    MMA16816(acc[mi][ni], ahi[mi], blo[ni]);
                }
        }
        __syncthreads();
    }

#pragma unroll
    for (int mi = 0; mi < 4; mi++) {
        int row = bm + warp_m * 64 + mi * 16 + (lane >> 2);
#pragma unroll
        for (int ni = 0; ni < 4; ni++) {
            int col = bn + warp_n * 32 + ni * 8 + (lane & 3) * 2;
            float b0 = bias[col], b1 = bias[col + 1];
            float2 v0 = make_float2(acc[mi][ni][0] + b0, acc[mi][ni][1] + b1);
            float2 v1 = make_float2(acc[mi][ni][2] + b0, acc[mi][ni][3] + b1);
            *(float2*)(C + (size_t)row * N + col) = v0;
            *(float2*)(C + (size_t)(row + 8) * N + col) = v1;
        }
    }
}

// ---------------------------------------------------------------------------
// Tensor-core flash attention (split-bf16 mma). One (t,h,128-q-tile) per CTA.
// 8 warps x 16 q-rows. K/V tiles of 64 keys. Online softmax in frag layout.
// SMEM rows stride 72 halfs (144B): frag LDS = single conflict-free 4B load.
// ---------------------------------------------------------------------------
#define QS 72
#define A_QH 0
#define A_QL (128 * QS)
#define A_KH (2 * 128 * QS)
#define A_KL (A_KH + 64 * QS)
#define A_VH (A_KL + 64 * QS)
#define A_VL (A_VH + 64 * QS)
#define ATTN_SMEM ((A_VL + 64 * QS) * 2)   // 73728 bytes

__global__ __launch_bounds__(256, 2) void attn_mma(
    const float* __restrict__ qkv, __nv_bfloat16* __restrict__ chi,
    __nv_bfloat16* __restrict__ clo)
{
    extern __shared__ __nv_bfloat16 sh[];
    const int tid = threadIdx.x;
    const int wid = tid >> 5, lane = tid & 31;
    const int q0 = blockIdx.x * 128;
    const int h  = blockIdx.y;
    const int t  = blockIdx.z;
    const size_t tbase = (size_t)t * B_DIM * D3 + h * HD_DIM;

    // ---- load Q tile (128 x 64), scale by 1/8, split hi/lo ----
    {
        const int r = tid >> 1;
        const int c0 = (tid & 1) * 32;
        const float* src = qkv + tbase + (size_t)(q0 + r) * D3 + c0;
        __nv_bfloat16* qh = sh + A_QH + r * QS + c0;
        __nv_bfloat16* ql = sh + A_QL + r * QS + c0;
#pragma unroll
        for (int j = 0; j < 32; j += 4) {
            float4 v = *(const float4*)(src + j);
            __nv_bfloat16 h0, h1, h2, h3, l0, l1, l2, l3;
            split2(v.x * 0.125f, h0, l0); split2(v.y * 0.125f, h1, l1);
            split2(v.z * 0.125f, h2, l2); split2(v.w * 0.125f, h3, l3);
            qh[j] = h0; qh[j + 1] = h1; qh[j + 2] = h2; qh[j + 3] = h3;
            ql[j] = l0; ql[j + 1] = l1; ql[j + 2] = l2; ql[j + 3] = l3;
        }
    }

    float m[2] = {-INFINITY, -INFINITY}, l[2] = {0.f, 0.f};
    float O[8][4];
#pragma unroll
    for (int dt = 0; dt < 8; dt++)
#pragma unroll
        for (int j = 0; j < 4; j++) O[dt][j] = 0.f;

    const int rA = lane >> 2;          // fragment row
    const int cA = (lane & 3) * 2;     // fragment col pair

    for (int kt = 0; kt < 8; ++kt) {
        __syncthreads();
        // ---- load K,V tile (64 keys x 64 d), split; V stored transposed ----
        {
            const int r = tid >> 2;
            const int c0 = (tid & 3) * 16;
            const float* ksrc = qkv + tbase + (size_t)(kt * 64 + r) * D3 + D_DIM + c0;
            const float* vsrc = ksrc + D_DIM;
            __nv_bfloat16* kh = sh + A_KH + r * QS + c0;
            __nv_bfloat16* kl = sh + A_KL + r * QS + c0;
#pragma unroll
            for (int j = 0; j < 16; j += 4) {
                float4 kv = *(const float4*)(ksrc + j);
                __nv_bfloat16 h0, h1, h2, h3, l0, l1, l2, l3;
                split2(kv.x, h0, l0); split2(kv.y, h1, l1);
                split2(kv.z, h2, l2); split2(kv.w, h3, l3);
                kh[j] = h0; kh[j + 1] = h1; kh[j + 2] = h2; kh[j + 3] = h3;
                kl[j] = l0; kl[j + 1] = l1; kl[j + 2] = l2; kl[j + 3] = l3;
                float4 vv = *(const float4*)(vsrc + j);
                split2(vv.x, h0, l0); split2(vv.y, h1, l1);
                split2(vv.z, h2, l2); split2(vv.w, h3, l3);
                sh[A_VH + (c0 + j + 0) * QS + r] = h0;
                sh[A_VH + (c0 + j + 1) * QS + r] = h1;
                sh[A_VH + (c0 + j + 2) * QS + r] = h2;
                sh[A_VH + (c0 + j + 3) * QS + r] = h3;
                sh[A_VL + (c0 + j + 0) * QS + r] = l0;
                sh[A_VL + (c0 + j + 1) * QS + r] = l1;
                sh[A_VL + (c0 + j + 2) * QS + r] = l2;
                sh[A_VL + (c0 + j + 3) * QS + r] = l3;
            }
        }
        __syncthreads();

        // ---- S = Q K^T (split-bf16, 3 passes), 16 rows x 64 keys per warp --
        float S[8][4];
#pragma unroll
        for (int nt = 0; nt < 8; nt++)
#pragma unroll
            for (int j = 0; j < 4; j++) S[nt][j] = 0.f;

#pragma unroll
        for (int kc = 0; kc < 4; ++kc) {
            const int ca = kc * 16 + cA;
            const int r0 = wid * 16 + rA;
            uint32_t qh[4], ql[4];
            qh[0] = *(const uint32_t*)&sh[A_QH + r0 * QS + ca];
            qh[1] = *(const uint32_t*)&sh[A_QH + (r0 + 8) * QS + ca];
            qh[2] = *(const uint32_t*)&sh[A_QH + r0 * QS + ca + 8];
            qh[3] = *(const uint32_t*)&sh[A_QH + (r0 + 8) * QS + ca + 8];
            ql[0] = *(const uint32_t*)&sh[A_QL + r0 * QS + ca];
            ql[1] = *(const uint32_t*)&sh[A_QL + (r0 + 8) * QS + ca];
            ql[2] = *(const uint32_t*)&sh[A_QL + r0 * QS + ca + 8];
            ql[3] = *(const uint32_t*)&sh[A_QL + (r0 + 8) * QS + ca + 8];
#pragma unroll
            for (int nt = 0; nt < 8; nt++) {
                const int kr = nt * 8 + rA;
                uint32_t kh[2], kl[2];
                kh[0] = *(const uint32_t*)&sh[A_KH + kr * QS + ca];
                kh[1] = *(const uint32_t*)&sh[A_KH + kr * QS + ca + 8];
                kl[0] = *(const uint32_t*)&sh[A_KL + kr * QS + ca];
                kl[1] = *(const uint32_t*)&sh[A_KL + kr * QS + ca + 8];
                MMA16816(S[nt], qh, kh);
                MMA16816(S[nt], ql, kh);
                MMA16816(S[nt], qh, kl);
            }
        }

        // ---- online softmax (rows rA and rA+8; quad-shfl reductions) ----
        float sf[2];
#pragma unroll
        for (int rh = 0; rh < 2; rh++) {
            float mv = m[rh];
#pragma unroll
            for (int nt = 0; nt < 8; nt++)
                mv = fmaxf(mv, fmaxf(S[nt][2 * rh], S[nt][2 * rh + 1]));
            mv = fmaxf(mv, __shfl_xor_sync(0xffffffffu, mv, 1));
            mv = fmaxf(mv, __shfl_xor_sync(0xffffffffu, mv, 2));
            sf[rh] = __expf(m[rh] - mv);
            m[rh] = mv;
            float rs = 0.f;
#pragma unroll
            for (int nt = 0; nt < 8; nt++) {
                float p0 = __expf(S[nt][2 * rh] - mv);
                float p1 = __expf(S[nt][2 * rh + 1] - mv);
                S[nt][2 * rh] = p0; S[nt][2 * rh + 1] = p1;
                rs += p0 + p1;
            }
            rs += __shfl_xor_sync(0xffffffffu, rs, 1);
            rs += __shfl_xor_sync(0xffffffffu, rs, 2);
            l[rh] = l[rh] * sf[rh] + rs;
        }
#pragma unroll
        for (int dt = 0; dt < 8; dt++) {
            O[dt][0] *= sf[0]; O[dt][1] *= sf[0];
            O[dt][2] *= sf[1]; O[dt][3] *= sf[1];
        }

        // ---- O += P V (split-bf16, 3 passes) ----
#pragma unroll
        for (int kc = 0; kc < 4; ++kc) {
            uint32_t ph[4], pl[4];
            {
                float p00 = S[2 * kc][0],     p01 = S[2 * kc][1];
                float p02 = S[2 * kc][2],     p03 = S[2 * kc][3];
                float p10 = S[2 * kc + 1][0], p11 = S[2 * kc + 1][1];
                float p12 = S[2 * kc + 1][2], p13 = S[2 * kc + 1][3];
                __nv_bfloat16 h0, h1, l0, l1;
                split2(p00, h0, l0); split2(p01, h1, l1);
                ph[0] = packbf(__bfloat162float(h0), __bfloat162float(h1));
                pl[0] = packbf(__bfloat162float(l0), __bfloat162float(l1));
                split2(p02, h0, l0); split2(p03, h1, l1);
                ph[1] = packbf(__bfloat162float(h0), __bfloat162float(h1));
                pl[1] = packbf(__bfloat162float(l0), __bfloat162float(l1));
                split2(p10, h0, l0); split2(p11, h1, l1);
                ph[2] = packbf(__bfloat162float(h0), __bfloat162float(h1));
                pl[2] = packbf(__bfloat162float(l0), __bfloat162float(l1));
                split2(p12, h0, l0); split2(p13, h1, l1);
                ph[3] = packbf(__bfloat162float(h0), __bfloat162float(h1));
                pl[3] = packbf(__bfloat162float(l0), __bfloat162float(l1));
            }
            const int ck = kc * 16 + cA;
#pragma unroll
            for (int dt = 0; dt < 8; dt++) {
                const int dr = dt * 8 + rA;
                uint32_t vh[2], vl[2];
                vh[0] = *(const uint32_t*)&sh[A_VH + dr * QS + ck];
                vh[1] = *(const uint32_t*)&sh[A_VH + dr * QS + ck + 8];
                vl[0] = *(const uint32_t*)&sh[A_VL + dr * QS + ck];
                vl[1] = *(const uint32_t*)&sh[A_VL + dr * QS + ck + 8];
                MMA16816(O[dt], ph, vh);
                MMA16816(O[dt], pl, vh);
                MMA16816(O[dt], ph, vl);
            }
        }
    }

    // ---- epilogue: normalize, split to bf16 hi/lo, store ctx ----
    float inv0 = 1.f / l[0], inv1 = 1.f / l[1];
#pragma unroll
    for (int rh = 0; rh < 2; rh++) {
        const float inv = rh ? inv1 : inv0;
        const int row = q0 + wid * 16 + rA + rh * 8;
        const size_t rb = ((size_t)t * B_DIM + row) * D_DIM + h * HD_DIM;
#pragma unroll
        for (int dt = 0; dt < 8; dt++) {
            float o0 = O[dt][2 * rh] * inv, o1 = O[dt][2 * rh + 1] * inv;
            __nv_bfloat16 h0, h1, l0, l1;
            split2(o0, h0, l0); split2(o1, h1, l1);
            __nv_bfloat162 ph; ph.x = h0; ph.y = h1;
            __nv_bfloat162 pL; pL.x = l0; pL.y = l1;
            *(__nv_bfloat162*)(chi + rb + dt * 8 + cA) = ph;
            *(__nv_bfloat162*)(clo + rb + dt * 8 + cA) = pL;
        }
    }
}

// ---------------------------------------------------------------------------
// Stage 4: adj[t,j] = (mean_i xn_i) . xn_j
// ---------------------------------------------------------------------------
__global__ __launch_bounds__(256) void rownorm_kernel(
    const float* __restrict__ x, float* __restrict__ inv)
{
    int warp = threadIdx.x >> 5, lane = threadIdx.x & 31;
    int row = blockIdx.x * 8 + warp;
    const float* p = x + (size_t)row * D_DIM;
    float s = 0.f;
    for (int d = lane; d < D_DIM; d += 32) { float v = p[d]; s = fmaf(v, v, s); }
#pragma unroll
    for (int o = 16; o > 0; o >>= 1) s += __shfl_xor_sync(0xffffffffu, s, o);
    if (lane == 0) inv[row] = 1.f / fmaxf(sqrtf(s), 1e-8f);
}

__global__ __launch_bounds__(256) void mean_kernel(
    const float* __restrict__ x, const float* __restrict__ inv,
    float* __restrict__ mean)
{
    __shared__ float sinv[B_DIM];
    int t = blockIdx.x;
    int d = blockIdx.y * 256 + threadIdx.x;
    for (int i = threadIdx.x; i < B_DIM; i += 256) sinv[i] = inv[t * B_DIM + i];
    __syncthreads();
    const float* p = x + (size_t)t * B_DIM * D_DIM + d;
    float s = 0.f;
    for (int i = 0; i < B_DIM; i++) s = fmaf(p[(size_t)i * D_DIM], sinv[i], s);
    mean[t * D_DIM + d] = s * (1.f / B_DIM);
}

__global__ __launch_bounds__(256) void adj_kernel(
    const float* __restrict__ x, const float* __restrict__ inv,
    const float* __restrict__ mean, float* __restrict__ out)
{
    int warp = threadIdx.x >> 5, lane = threadIdx.x & 31;
    int row = blockIdx.x * 8 + warp;
    int t = row >> 9;
    const float* p = x + (size_t)row * D_DIM;
    const float* mp = mean + t * D_DIM;
    float s = 0.f;
    for (int d = lane; d < D_DIM; d += 32) s = fmaf(p[d], mp[d], s);
#pragma unroll
    for (int o = 16; o > 0; o >>= 1) s += __shfl_xor_sync(0xffffffffu, s, o);
    if (lane == 0) out[row] = s * inv[row];
}

// ---------------------------------------------------------------------------
extern "C" void kernel_launch(void* const* d_in, const int* in_sizes, int n_in,
                              void* d_out, int out_size)
{
    const float* node  = (const float*)d_in[0];
    const float* w_in  = (const float*)d_in[1];
    const float* b_in  = (const float*)d_in[2];
    const float* w_out = (const float*)d_in[3];
    const float* b_out = (const float*)d_in[4];
    float* out = (float*)d_out;

    float *qkv, *o, *inv, *mean;
    __nv_bfloat16 *nhi, *nlo, *chi, *clo, *wihi, *wilo, *wohi, *wolo;
    cudaGetSymbolAddress((void**)&qkv,  g_qkv);
    cudaGetSymbolAddress((void**)&o,    g_out);
    cudaGetSymbolAddress((void**)&inv,  g_inv);
    cudaGetSymbolAddress((void**)&mean, g_mean);
    cudaGetSymbolAddress((void**)&nhi,  g_nhi);
    cudaGetSymbolAddress((void**)&nlo,  g_nlo);
    cudaGetSymbolAddress((void**)&chi,  g_chi);
    cudaGetSymbolAddress((void**)&clo,  g_clo);
    cudaGetSymbolAddress((void**)&wihi, g_wihi);
    cudaGetSymbolAddress((void**)&wilo, g_wilo);
    cudaGetSymbolAddress((void**)&wohi, g_wohi);
    cudaGetSymbolAddress((void**)&wolo, g_wolo);

    cudaFuncSetAttribute(gemm_mma,
                         cudaFuncAttributeMaxDynamicSharedMemorySize, GEMM_SMEM);
    cudaFuncSetAttribute(attn_mma,
                         cudaFuncAttributeMaxDynamicSharedMemorySize, ATTN_SMEM);

    const int n_node = M_DIM * D_DIM;
    const int n_wi   = D3 * D_DIM;
    const int n_wo   = D_DIM * D_DIM;

    // 0) split fp32 -> bf16 hi/lo
    split_kernel<<<n_node / 1024, 256>>>(node, nhi, nlo, n_node);
    split_kernel<<<n_wi   / 1024, 256>>>(w_in, wihi, wilo, n_wi);
    split_kernel<<<n_wo   / 1024, 256>>>(w_out, wohi, wolo, n_wo);
    // 1) QKV projection (mma.sync split-bf16)
    gemm_mma<<<dim3(D3 / 128, M_DIM / 128), 256, GEMM_SMEM>>>(
        nhi, nlo, wihi, wilo, b_in, qkv, D3, D_DIM);
    // 2) Tensor-core flash attention (writes ctx as bf16 hi/lo)
    attn_mma<<<dim3(B_DIM / 128, H_DIM, T_DIM), 256, ATTN_SMEM>>>(qkv, chi, clo);
    // 3) Output projection
    gemm_mma<<<dim3(D_DIM / 128, M_DIM / 128), 256, GEMM_SMEM>>>(
        chi, clo, wohi, wolo, b_out, o, D_DIM, D_DIM);
    // 4) adjacency
    rownorm_kernel<<<M_DIM / 8, 256>>>(o, inv);
    mean_kernel<<<dim3(T_DIM, D_DIM / 256), 256>>>(o, inv, mean);
    adj_kernel<<<M_DIM / 8, 256>>>(o, inv, mean, out);
}

// round 14
// speedup vs baseline: 2.5755x; 1.0816x over previous
#include <cuda_runtime.h>
#include <cuda_bf16.h>
#include <math.h>
#include <stdint.h>

#define T_DIM 64
#define B_DIM 512
#define D_DIM 768
#define H_DIM 12
#define HD_DIM 64
#define D3 (3 * D_DIM)
#define M_DIM (T_DIM * B_DIM)   // 32768

// ---------------------------------------------------------------------------
// Scratch (allocation-free rule: __device__ globals)
// ---------------------------------------------------------------------------
__device__ __nv_bfloat16 g_qkvh[(size_t)M_DIM * D3];        // qkv hi (bf16)
__device__ __nv_bfloat16 g_qkvl[(size_t)M_DIM * D3];        // qkv lo
__device__ float g_out[(size_t)M_DIM * D_DIM];              // 100 MB fp32
__device__ __nv_bfloat16 g_nhi[(size_t)M_DIM * D_DIM];
__device__ __nv_bfloat16 g_nlo[(size_t)M_DIM * D_DIM];
__device__ __nv_bfloat16 g_chi[(size_t)M_DIM * D_DIM];
__device__ __nv_bfloat16 g_clo[(size_t)M_DIM * D_DIM];
__device__ __nv_bfloat16 g_wihi[(size_t)D3 * D_DIM];
__device__ __nv_bfloat16 g_wilo[(size_t)D3 * D_DIM];
__device__ __nv_bfloat16 g_wohi[(size_t)D_DIM * D_DIM];
__device__ __nv_bfloat16 g_wolo[(size_t)D_DIM * D_DIM];
__device__ float g_inv[M_DIM];
__device__ float g_mean[T_DIM * D_DIM];

// ---------------------------------------------------------------------------
// Portable PTX helpers (compute_103 virtual arch: mma.sync/ldmatrix/cp.async)
// ---------------------------------------------------------------------------
__device__ __forceinline__ void cpa16(uint32_t dst, const void* src) {
    asm volatile("cp.async.cg.shared.global [%0], [%1], 16;"
                 :: "r"(dst), "l"(src) : "memory");
}
__device__ __forceinline__ void cpa_commit() {
    asm volatile("cp.async.commit_group;" ::: "memory");
}
__device__ __forceinline__ void cpa_wait0() {
    asm volatile("cp.async.wait_group 0;" ::: "memory");
}

#define MMA16816(d, a, b)                                                   \
    asm volatile(                                                           \
        "mma.sync.aligned.m16n8k16.row.col.f32.bf16.bf16.f32 "             \
        "{%0,%1,%2,%3}, {%4,%5,%6,%7}, {%8,%9}, {%0,%1,%2,%3};"            \
        : "+f"((d)[0]), "+f"((d)[1]), "+f"((d)[2]), "+f"((d)[3])            \
        : "r"((a)[0]), "r"((a)[1]), "r"((a)[2]), "r"((a)[3]),               \
          "r"((b)[0]), "r"((b)[1]))

#define LDSM4(r, addr)                                                      \
    asm volatile("ldmatrix.sync.aligned.m8n8.x4.shared.b16 {%0,%1,%2,%3}, [%4];" \
        : "=r"((r)[0]), "=r"((r)[1]), "=r"((r)[2]), "=r"((r)[3]) : "r"(addr))

__device__ __forceinline__ void split2(float v, __nv_bfloat16& h, __nv_bfloat16& l) {
    h = __float2bfloat16(v);
    l = __float2bfloat16(v - __bfloat162float(h));
}
__device__ __forceinline__ uint32_t packbf(float a, float b) {
    __nv_bfloat162 t; t.x = __float2bfloat16(a); t.y = __float2bfloat16(b);
    return *(uint32_t*)&t;
}

// ---------------------------------------------------------------------------
// fp32 -> bf16 hi/lo split (elementwise)
// ---------------------------------------------------------------------------
__global__ __launch_bounds__(256) void split_kernel(
    const float* __restrict__ x, __nv_bfloat16* __restrict__ hi,
    __nv_bfloat16* __restrict__ lo, int n)
{
    int i = (blockIdx.x * 256 + threadIdx.x) * 4;
    if (i >= n) return;
    float4 v = *(const float4*)(x + i);
    __nv_bfloat16 h0, h1, h2, h3, l0, l1, l2, l3;
    split2(v.x, h0, l0); split2(v.y, h1, l1);
    split2(v.z, h2, l2); split2(v.w, h3, l3);
    __nv_bfloat162 hh0; hh0.x = h0; hh0.y = h1;
    __nv_bfloat162 hh1; hh1.x = h2; hh1.y = h3;
    __nv_bfloat162 ll0; ll0.x = l0; ll0.y = l1;
    __nv_bfloat162 ll1; ll1.x = l2; ll1.y = l3;
    *(__nv_bfloat162*)(hi + i)     = hh0;
    *(__nv_bfloat162*)(hi + i + 2) = hh1;
    *(__nv_bfloat162*)(lo + i)     = ll0;
    *(__nv_bfloat162*)(lo + i + 2) = ll1;
}

// ---------------------------------------------------------------------------
// mma.sync split-bf16 GEMM (NT): C = A*B^T + bias ; C = AhBh + AlBh + AhBl
// 128x128 block, BK=32, 8 warps (2Mx4N), cp.async double buffer, ldmatrix
// fragment loads. SPLIT_OUT=1 writes bf16 hi/lo (for QKV), else fp32.
// ---------------------------------------------------------------------------
#define SA 40
#define TILE_H (128 * SA)
#define GEMM_SMEM (2 * 4 * TILE_H * 2)

template <int SPLIT_OUT>
__global__ __launch_bounds__(256, 2) void gemm_mma(
    const __nv_bfloat16* __restrict__ Ahi, const __nv_bfloat16* __restrict__ Alo,
    const __nv_bfloat16* __restrict__ Bhi, const __nv_bfloat16* __restrict__ Blo,
    const float* __restrict__ bias, float* __restrict__ C,
    __nv_bfloat16* __restrict__ Chi, __nv_bfloat16* __restrict__ Clo,
    int N, int K)
{
    extern __shared__ __nv_bfloat16 sh[];
    const uint32_t sbase = (uint32_t)__cvta_generic_to_shared(sh);
    const int tid = threadIdx.x;
    const int wid = tid >> 5, lane = tid & 31;
    const int warp_m = wid >> 2, warp_n = wid & 3;
    const int bm = blockIdx.y * 128, bn = blockIdx.x * 128;

    const int lrow = tid >> 1;
    const int lofs = (tid & 1) * 16;
    const __nv_bfloat16* srcs[4];
    srcs[0] = Ahi + (size_t)(bm + lrow) * K + lofs;
    srcs[1] = Alo + (size_t)(bm + lrow) * K + lofs;
    srcs[2] = Bhi + (size_t)(bn + lrow) * K + lofs;
    srcs[3] = Blo + (size_t)(bn + lrow) * K + lofs;
    const uint32_t sdst = sbase + (uint32_t)(lrow * SA + lofs) * 2;

    // ldmatrix per-lane byte offsets within a tile
    const uint32_t a_loff =
        (uint32_t)(((warp_m * 64 + (lane & 15)) * SA + (lane >> 4) * 8) * 2);
    const uint32_t b_loff =
        (uint32_t)(((warp_n * 32 + (lane & 7) + ((lane >> 4) & 1) * 8) * SA +
                    ((lane >> 3) & 1) * 8) * 2);

    const int nchunks = K >> 5;

#pragma unroll
    for (int tI = 0; tI < 4; tI++) {
        uint32_t d = sdst + tI * TILE_H * 2;
        cpa16(d, srcs[tI]);
        cpa16(d + 16, srcs[tI] + 8);
    }
    cpa_commit();

    float acc[4][4][4];
#pragma unroll
    for (int mi = 0; mi < 4; mi++)
#pragma unroll
        for (int ni = 0; ni < 4; ni++)
#pragma unroll
            for (int j = 0; j < 4; j++) acc[mi][ni][j] = 0.f;

    for (int c = 0; c < nchunks; ++c) {
        cpa_wait0();
        __syncthreads();

        if (c + 1 < nchunks) {
            const int s1 = (c + 1) & 1;
            const int ko = (c + 1) * 32;
#pragma unroll
            for (int tI = 0; tI < 4; tI++) {
                uint32_t d = sdst + (s1 * 4 + tI) * TILE_H * 2;
                cpa16(d, srcs[tI] + ko);
                cpa16(d + 16, srcs[tI] + ko + 8);
            }
            cpa_commit();
        }

        const uint32_t st   = sbase + (uint32_t)((c & 1) * 4) * TILE_H * 2;
        const uint32_t uAhi = st;
        const uint32_t uAlo = st + TILE_H * 2;
        const uint32_t uBhi = st + 2 * TILE_H * 2;
        const uint32_t uBlo = st + 3 * TILE_H * 2;

#pragma unroll
        for (int ks = 0; ks < 2; ++ks) {
            const uint32_t ko = ks * 32;   // 16 halfs
            uint32_t ahi[4][4], alo[4][4], bhi[4][2], blo[4][2];
#pragma unroll
            for (int mi = 0; mi < 4; mi++) {
                LDSM4(ahi[mi], uAhi + a_loff + mi * (16 * SA * 2) + ko);
                LDSM4(alo[mi], uAlo + a_loff + mi * (16 * SA * 2) + ko);
            }
#pragma unroll
            for (int np = 0; np < 2; np++) {
                uint32_t tb[4];
                LDSM4(tb, uBhi + b_loff + np * (16 * SA * 2) + ko);
                bhi[2 * np][0] = tb[0]; bhi[2 * np][1] = tb[1];
                bhi[2 * np + 1][0] = tb[2]; bhi[2 * np + 1][1] = tb[3];
                LDSM4(tb, uBlo + b_loff + np * (16 * SA * 2) + ko);
                blo[2 * np][0] = tb[0]; blo[2 * np][1] = tb[1];
                blo[2 * np + 1][0] = tb[2]; blo[2 * np + 1][1] = tb[3];
            }
#pragma unroll
            for (int mi = 0; mi < 4; mi++)
#pragma unroll
                for (int ni = 0; ni < 4; ni++) {
                    MMA16816(acc[mi][ni], ahi[mi], bhi[ni]);
                    MMA16816(acc[mi][ni], alo[mi], bhi[ni]);
                    MMA16816(acc[mi][ni], ahi[mi], blo[ni]);
                }
        }
        __syncthreads();
    }

#pragma unroll
    for (int mi = 0; mi < 4; mi++) {
        int row = bm + warp_m * 64 + mi * 16 + (lane >> 2);
#pragma unroll
        for (int ni = 0; ni < 4; ni++) {
            int col = bn + warp_n * 32 + ni * 8 + (lane & 3) * 2;
            float b0 = bias[col], b1 = bias[col + 1];
            float o0 = acc[mi][ni][0] + b0, o1 = acc[mi][ni][1] + b1;
            float o2 = acc[mi][ni][2] + b0, o3 = acc[mi][ni][3] + b1;
            if (SPLIT_OUT) {
                __nv_bfloat16 h0, h1, l0, l1;
                split2(o0, h0, l0); split2(o1, h1, l1);
                __nv_bfloat162 ph; ph.x = h0; ph.y = h1;
                __nv_bfloat162 pl; pl.x = l0; pl.y = l1;
                *(__nv_bfloat162*)(Chi + (size_t)row * N + col) = ph;
                *(__nv_bfloat162*)(Clo + (size_t)row * N + col) = pl;
                split2(o2, h0, l0); split2(o3, h1, l1);
                ph.x = h0; ph.y = h1; pl.x = l0; pl.y = l1;
                *(__nv_bfloat162*)(Chi + (size_t)(row + 8) * N + col) = ph;
                *(__nv_bfloat162*)(Clo + (size_t)(row + 8) * N + col) = pl;
            } else {
                *(float2*)(C + (size_t)row * N + col) = make_float2(o0, o1);
                *(float2*)(C + (size_t)(row + 8) * N + col) = make_float2(o2, o3);
            }
        }
    }
}

// ---------------------------------------------------------------------------
// Tensor-core flash attention on pre-split bf16 qkv. One (t,h,128q) per CTA.
// cp.async raw hi/lo Q,K tiles; V transposed via LDG+STS. ldmatrix frags.
// Scale 1/8 applied to S post-MMA (exact power of two).
// ---------------------------------------------------------------------------
#define QS 72
#define A_QH 0
#define A_QL (128 * QS)
#define A_KH (2 * 128 * QS)
#define A_KL (A_KH + 64 * QS)
#define A_VH (A_KL + 64 * QS)
#define A_VL (A_VH + 64 * QS)
#define ATTN_SMEM ((A_VL + 64 * QS) * 2)   // 73728 bytes

__global__ __launch_bounds__(256, 2) void attn_mma(
    const __nv_bfloat16* __restrict__ qkvh,
    const __nv_bfloat16* __restrict__ qkvl,
    __nv_bfloat16* __restrict__ chi, __nv_bfloat16* __restrict__ clo)
{
    extern __shared__ __nv_bfloat16 sh[];
    const uint32_t sbase = (uint32_t)__cvta_generic_to_shared(sh);
    const int tid = threadIdx.x;
    const int wid = tid >> 5, lane = tid & 31;
    const int q0 = blockIdx.x * 128;
    const int h  = blockIdx.y;
    const int t  = blockIdx.z;
    const size_t tbase = (size_t)t * B_DIM * D3 + h * HD_DIM;

    // ---- Q tile (128 x 64 halfs) raw cp.async, hi + lo ----
    {
        const int r = tid >> 1, c0 = (tid & 1) * 32;
        const __nv_bfloat16* sh_src = qkvh + tbase + (size_t)(q0 + r) * D3 + c0;
        const __nv_bfloat16* sl_src = qkvl + tbase + (size_t)(q0 + r) * D3 + c0;
        const uint32_t dh = sbase + (uint32_t)(A_QH + r * QS + c0) * 2;
        const uint32_t dl = sbase + (uint32_t)(A_QL + r * QS + c0) * 2;
#pragma unroll
        for (int j = 0; j < 4; j++) {
            cpa16(dh + j * 16, sh_src + j * 8);
            cpa16(dl + j * 16, sl_src + j * 8);
        }
        cpa_commit();
    }

    // ldmatrix lane offsets (bytes)
    const uint32_t q_loff =
        (uint32_t)(((wid * 16 + (lane & 15)) * QS + (lane >> 4) * 8) * 2);
    const uint32_t kv_loff =
        (uint32_t)((((lane & 7) + ((lane >> 4) & 1) * 8) * QS +
                    ((lane >> 3) & 1) * 8) * 2);
    const uint32_t uQH = sbase + A_QH * 2, uQL = sbase + A_QL * 2;
    const uint32_t uKH = sbase + A_KH * 2, uKL = sbase + A_KL * 2;
    const uint32_t uVH = sbase + A_VH * 2, uVL = sbase + A_VL * 2;

    float m[2] = {-INFINITY, -INFINITY}, l[2] = {0.f, 0.f};
    float O[8][4];
#pragma unroll
    for (int dt = 0; dt < 8; dt++)
#pragma unroll
        for (int j = 0; j < 4; j++) O[dt][j] = 0.f;

    const int cA = (lane & 3) * 2;
    const int rA = lane >> 2;

    for (int kt = 0; kt < 8; ++kt) {
        __syncthreads();
        // ---- K tile cp.async (raw hi/lo), V tile transposed via LDG+STS ----
        {
            const int kr = tid >> 2, kc0 = (tid & 3) * 16;
            const size_t rowb = tbase + (size_t)(kt * 64 + kr) * D3;
            const __nv_bfloat16* kh_src = qkvh + rowb + D_DIM + kc0;
            const __nv_bfloat16* kl_src = qkvl + rowb + D_DIM + kc0;
            const uint32_t dh = sbase + (uint32_t)(A_KH + kr * QS + kc0) * 2;
            const uint32_t dl = sbase + (uint32_t)(A_KL + kr * QS + kc0) * 2;
            cpa16(dh, kh_src); cpa16(dh + 16, kh_src + 8);
            cpa16(dl, kl_src); cpa16(dl + 16, kl_src + 8);

            const __nv_bfloat16* vh_src = qkvh + rowb + 2 * D_DIM + kc0;
            const __nv_bfloat16* vl_src = qkvl + rowb + 2 * D_DIM + kc0;
            uint4 u0 = *(const uint4*)(vh_src);
            uint4 u1 = *(const uint4*)(vh_src + 8);
            const __nv_bfloat16* e0 = (const __nv_bfloat16*)&u0;
            const __nv_bfloat16* e1 = (const __nv_bfloat16*)&u1;
#pragma unroll
            for (int j = 0; j < 8; j++) {
                sh[A_VH + (kc0 + j) * QS + kr] = e0[j];
                sh[A_VH + (kc0 + 8 + j) * QS + kr] = e1[j];
            }
            u0 = *(const uint4*)(vl_src);
            u1 = *(const uint4*)(vl_src + 8);
#pragma unroll
            for (int j = 0; j < 8; j++) {
                sh[A_VL + (kc0 + j) * QS + kr] = e0[j];
                sh[A_VL + (kc0 + 8 + j) * QS + kr] = e1[j];
            }
            cpa_commit();
        }
        cpa_wait0();
        __syncthreads();

        // ---- S = Q K^T (3-pass split), ldmatrix frags ----
        float S[8][4];
#pragma unroll
        for (int nt = 0; nt < 8; nt++)
#pragma unroll
            for (int j = 0; j < 4; j++) S[nt][j] = 0.f;

#pragma unroll
        for (int kc = 0; kc < 4; ++kc) {
            const uint32_t ko = kc * 32;
            uint32_t qh[4], ql[4];
            LDSM4(qh, uQH + q_loff + ko);
            LDSM4(ql, uQL + q_loff + ko);
#pragma unroll
            for (int np = 0; np < 4; np++) {
                uint32_t th[4], tl[4];
                LDSM4(th, uKH + kv_loff + np * (16 * QS * 2) + ko);
                LDSM4(tl, uKL + kv_loff + np * (16 * QS * 2) + ko);
                uint32_t kh0[2] = {th[0], th[1]}, kh1[2] = {th[2], th[3]};
                uint32_t kl0[2] = {tl[0], tl[1]}, kl1[2] = {tl[2], tl[3]};
                MMA16816(S[2 * np], qh, kh0);
                MMA16816(S[2 * np], ql, kh0);
                MMA16816(S[2 * np], qh, kl0);
                MMA16816(S[2 * np + 1], qh, kh1);
                MMA16816(S[2 * np + 1], ql, kh1);
                MMA16816(S[2 * np + 1], qh, kl1);
            }
        }
#pragma unroll
        for (int nt = 0; nt < 8; nt++)
#pragma unroll
            for (int j = 0; j < 4; j++) S[nt][j] *= 0.125f;

        // ---- online softmax ----
        float sf[2];
#pragma unroll
        for (int rh = 0; rh < 2; rh++) {
            float mv = m[rh];
#pragma unroll
            for (int nt = 0; nt < 8; nt++)
                mv = fmaxf(mv, fmaxf(S[nt][2 * rh], S[nt][2 * rh + 1]));
            mv = fmaxf(mv, __shfl_xor_sync(0xffffffffu, mv, 1));
            mv = fmaxf(mv, __shfl_xor_sync(0xffffffffu, mv, 2));
            sf[rh] = __expf(m[rh] - mv);
            m[rh] = mv;
            float rs = 0.f;
#pragma unroll
            for (int nt = 0; nt < 8; nt++) {
                float p0 = __expf(S[nt][2 * rh] - mv);
                float p1 = __expf(S[nt][2 * rh + 1] - mv);
                S[nt][2 * rh] = p0; S[nt][2 * rh + 1] = p1;
                rs += p0 + p1;
            }
            rs += __shfl_xor_sync(0xffffffffu, rs, 1);
            rs += __shfl_xor_sync(0xffffffffu, rs, 2);
            l[rh] = l[rh] * sf[rh] + rs;
        }
#pragma unroll
        for (int dt = 0; dt < 8; dt++) {
            O[dt][0] *= sf[0]; O[dt][1] *= sf[0];
            O[dt][2] *= sf[1]; O[dt][3] *= sf[1];
        }

        // ---- O += P V (3-pass split) ----
#pragma unroll
        for (int kc = 0; kc < 4; ++kc) {
            uint32_t ph[4], pl[4];
            {
                __nv_bfloat16 h0, h1, l0, l1;
                split2(S[2 * kc][0], h0, l0); split2(S[2 * kc][1], h1, l1);
                ph[0] = packbf(__bfloat162float(h0), __bfloat162float(h1));
                pl[0] = packbf(__bfloat162float(l0), __bfloat162float(l1));
                split2(S[2 * kc][2], h0, l0); split2(S[2 * kc][3], h1, l1);
                ph[1] = packbf(__bfloat162float(h0), __bfloat162float(h1));
                pl[1] = packbf(__bfloat162float(l0), __bfloat162float(l1));
                split2(S[2 * kc + 1][0], h0, l0); split2(S[2 * kc + 1][1], h1, l1);
                ph[2] = packbf(__bfloat162float(h0), __bfloat162float(h1));
                pl[2] = packbf(__bfloat162float(l0), __bfloat162float(l1));
                split2(S[2 * kc + 1][2], h0, l0); split2(S[2 * kc + 1][3], h1, l1);
                ph[3] = packbf(__bfloat162float(h0), __bfloat162float(h1));
                pl[3] = packbf(__bfloat162float(l0), __bfloat162float(l1));
            }
            const uint32_t ko = kc * 32;
#pragma unroll
            for (int dp = 0; dp < 4; dp++) {
                uint32_t th[4], tl[4];
                LDSM4(th, uVH + kv_loff + dp * (16 * QS * 2) + ko);
                LDSM4(tl, uVL + kv_loff + dp * (16 * QS * 2) + ko);
                uint32_t vh0[2] = {th[0], th[1]}, vh1[2] = {th[2], th[3]};
                uint32_t vl0[2] = {tl[0], tl[1]}, vl1[2] = {tl[2], tl[3]};
                MMA16816(O[2 * dp], ph, vh0);
                MMA16816(O[2 * dp], pl, vh0);
                MMA16816(O[2 * dp], ph, vl0);
                MMA16816(O[2 * dp + 1], ph, vh1);
                MMA16816(O[2 * dp + 1], pl, vh1);
                MMA16816(O[2 * dp + 1], ph, vl1);
            }
        }
    }

    // ---- epilogue ----
    float inv0 = 1.f / l[0], inv1 = 1.f / l[1];
#pragma unroll
    for (int rh = 0; rh < 2; rh++) {
        const float inv = rh ? inv1 : inv0;
        const int row = q0 + wid * 16 + rA + rh * 8;
        const size_t rb = ((size_t)t * B_DIM + row) * D_DIM + h * HD_DIM;
#pragma unroll
        for (int dt = 0; dt < 8; dt++) {
            float o0 = O[dt][2 * rh] * inv, o1 = O[dt][2 * rh + 1] * inv;
            __nv_bfloat16 h0, h1, l0, l1;
            split2(o0, h0, l0); split2(o1, h1, l1);
            __nv_bfloat162 ph; ph.x = h0; ph.y = h1;
            __nv_bfloat162 pL; pL.x = l0; pL.y = l1;
            *(__nv_bfloat162*)(chi + rb + dt * 8 + cA) = ph;
            *(__nv_bfloat162*)(clo + rb + dt * 8 + cA) = pL;
        }
    }
}

// ---------------------------------------------------------------------------
// Stage 4: adj[t,j] = (mean_i xn_i) . xn_j
// ---------------------------------------------------------------------------
__global__ __launch_bounds__(256) void rownorm_kernel(
    const float* __restrict__ x, float* __restrict__ inv)
{
    int warp = threadIdx.x >> 5, lane = threadIdx.x & 31;
    int row = blockIdx.x * 8 + warp;
    const float* p = x + (size_t)row * D_DIM;
    float s = 0.f;
    for (int d = lane; d < D_DIM; d += 32) { float v = p[d]; s = fmaf(v, v, s); }
#pragma unroll
    for (int o = 16; o > 0; o >>= 1) s += __shfl_xor_sync(0xffffffffu, s, o);
    if (lane == 0) inv[row] = 1.f / fmaxf(sqrtf(s), 1e-8f);
}

__global__ __launch_bounds__(256) void mean_kernel(
    const float* __restrict__ x, const float* __restrict__ inv,
    float* __restrict__ mean)
{
    __shared__ float sinv[B_DIM];
    int t = blockIdx.x;
    int d = blockIdx.y * 256 + threadIdx.x;
    for (int i = threadIdx.x; i < B_DIM; i += 256) sinv[i] = inv[t * B_DIM + i];
    __syncthreads();
    const float* p = x + (size_t)t * B_DIM * D_DIM + d;
    float s = 0.f;
    for (int i = 0; i < B_DIM; i++) s = fmaf(p[(size_t)i * D_DIM], sinv[i], s);
    mean[t * D_DIM + d] = s * (1.f / B_DIM);
}

__global__ __launch_bounds__(256) void adj_kernel(
    const float* __restrict__ x, const float* __restrict__ inv,
    const float* __restrict__ mean, float* __restrict__ out)
{
    int warp = threadIdx.x >> 5, lane = threadIdx.x & 31;
    int row = blockIdx.x * 8 + warp;
    int t = row >> 9;
    const float* p = x + (size_t)row * D_DIM;
    const float* mp = mean + t * D_DIM;
    float s = 0.f;
    for (int d = lane; d < D_DIM; d += 32) s = fmaf(p[d], mp[d], s);
#pragma unroll
    for (int o = 16; o > 0; o >>= 1) s += __shfl_xor_sync(0xffffffffu, s, o);
    if (lane == 0) out[row] = s * inv[row];
}

// ---------------------------------------------------------------------------
extern "C" void kernel_launch(void* const* d_in, const int* in_sizes, int n_in,
                              void* d_out, int out_size)
{
    const float* node  = (const float*)d_in[0];
    const float* w_in  = (const float*)d_in[1];
    const float* b_in  = (const float*)d_in[2];
    const float* w_out = (const float*)d_in[3];
    const float* b_out = (const float*)d_in[4];
    float* out = (float*)d_out;

    float *o, *inv, *mean;
    __nv_bfloat16 *qkvh, *qkvl, *nhi, *nlo, *chi, *clo, *wihi, *wilo, *wohi, *wolo;
    cudaGetSymbolAddress((void**)&qkvh, g_qkvh);
    cudaGetSymbolAddress((void**)&qkvl, g_qkvl);
    cudaGetSymbolAddress((void**)&o,    g_out);
    cudaGetSymbolAddress((void**)&inv,  g_inv);
    cudaGetSymbolAddress((void**)&mean, g_mean);
    cudaGetSymbolAddress((void**)&nhi,  g_nhi);
    cudaGetSymbolAddress((void**)&nlo,  g_nlo);
    cudaGetSymbolAddress((void**)&chi,  g_chi);
    cudaGetSymbolAddress((void**)&clo,  g_clo);
    cudaGetSymbolAddress((void**)&wihi, g_wihi);
    cudaGetSymbolAddress((void**)&wilo, g_wilo);
    cudaGetSymbolAddress((void**)&wohi, g_wohi);
    cudaGetSymbolAddress((void**)&wolo, g_wolo);

    cudaFuncSetAttribute(gemm_mma<0>,
                         cudaFuncAttributeMaxDynamicSharedMemorySize, GEMM_SMEM);
    cudaFuncSetAttribute(gemm_mma<1>,
                         cudaFuncAttributeMaxDynamicSharedMemorySize, GEMM_SMEM);
    cudaFuncSetAttribute(attn_mma,
                         cudaFuncAttributeMaxDynamicSharedMemorySize, ATTN_SMEM);

    const int n_node = M_DIM * D_DIM;
    const int n_wi   = D3 * D_DIM;
    const int n_wo   = D_DIM * D_DIM;

    // 0) split fp32 -> bf16 hi/lo
    split_kernel<<<n_node / 1024, 256>>>(node, nhi, nlo, n_node);
    split_kernel<<<n_wi   / 1024, 256>>>(w_in, wihi, wilo, n_wi);
    split_kernel<<<n_wo   / 1024, 256>>>(w_out, wohi, wolo, n_wo);
    // 1) QKV projection -> bf16 hi/lo directly
    gemm_mma<1><<<dim3(D3 / 128, M_DIM / 128), 256, GEMM_SMEM>>>(
        nhi, nlo, wihi, wilo, b_in, nullptr, qkvh, qkvl, D3, D_DIM);
    // 2) Tensor-core flash attention (pre-split qkv in, split ctx out)
    attn_mma<<<dim3(B_DIM / 128, H_DIM, T_DIM), 256, ATTN_SMEM>>>(
        qkvh, qkvl, chi, clo);
    // 3) Output projection -> fp32
    gemm_mma<0><<<dim3(D_DIM / 128, M_DIM / 128), 256, GEMM_SMEM>>>(
        chi, clo, wohi, wolo, b_out, o, nullptr, nullptr, D_DIM, D_DIM);
    // 4) adjacency
    rownorm_kernel<<<M_DIM / 8, 256>>>(o, inv);
    mean_kernel<<<dim3(T_DIM, D_DIM / 256), 256>>>(o, inv, mean);
    adj_kernel<<<M_DIM / 8, 256>>>(o, inv, mean, out);
}

// round 15
// speedup vs baseline: 2.6990x; 1.0479x over previous
#include <cuda_runtime.h>
#include <cuda_bf16.h>
#include <math.h>
#include <stdint.h>

#define T_DIM 64
#define B_DIM 512
#define D_DIM 768
#define H_DIM 12
#define HD_DIM 64
#define D3 (3 * D_DIM)
#define M_DIM (T_DIM * B_DIM)   // 32768

// ---------------------------------------------------------------------------
// Scratch (allocation-free rule: __device__ globals)
// ---------------------------------------------------------------------------
__device__ __nv_bfloat16 g_qkvh[(size_t)M_DIM * D3];
__device__ __nv_bfloat16 g_qkvl[(size_t)M_DIM * D3];
__device__ float g_out[(size_t)M_DIM * D_DIM];
__device__ __nv_bfloat16 g_nhi[(size_t)M_DIM * D_DIM];
__device__ __nv_bfloat16 g_nlo[(size_t)M_DIM * D_DIM];
__device__ __nv_bfloat16 g_chi[(size_t)M_DIM * D_DIM];
__device__ __nv_bfloat16 g_clo[(size_t)M_DIM * D_DIM];
__device__ __nv_bfloat16 g_wihi[(size_t)D3 * D_DIM];
__device__ __nv_bfloat16 g_wilo[(size_t)D3 * D_DIM];
__device__ __nv_bfloat16 g_wohi[(size_t)D_DIM * D_DIM];
__device__ __nv_bfloat16 g_wolo[(size_t)D_DIM * D_DIM];
__device__ float g_inv[M_DIM];
__device__ float g_mean[T_DIM * D_DIM];

// ---------------------------------------------------------------------------
// Portable PTX helpers
// ---------------------------------------------------------------------------
__device__ __forceinline__ void cpa16(uint32_t dst, const void* src) {
    asm volatile("cp.async.cg.shared.global [%0], [%1], 16;"
                 :: "r"(dst), "l"(src) : "memory");
}
__device__ __forceinline__ void cpa_commit() {
    asm volatile("cp.async.commit_group;" ::: "memory");
}
__device__ __forceinline__ void cpa_wait0() {
    asm volatile("cp.async.wait_group 0;" ::: "memory");
}

#define MMA16816(d, a, b)                                                   \
    asm volatile(                                                           \
        "mma.sync.aligned.m16n8k16.row.col.f32.bf16.bf16.f32 "             \
        "{%0,%1,%2,%3}, {%4,%5,%6,%7}, {%8,%9}, {%0,%1,%2,%3};"            \
        : "+f"((d)[0]), "+f"((d)[1]), "+f"((d)[2]), "+f"((d)[3])            \
        : "r"((a)[0]), "r"((a)[1]), "r"((a)[2]), "r"((a)[3]),               \
          "r"((b)[0]), "r"((b)[1]))

#define LDSM4(r, addr)                                                      \
    asm volatile("ldmatrix.sync.aligned.m8n8.x4.shared.b16 {%0,%1,%2,%3}, [%4];" \
        : "=r"((r)[0]), "=r"((r)[1]), "=r"((r)[2]), "=r"((r)[3]) : "r"(addr))

#define LDSM4T(r, addr)                                                     \
    asm volatile("ldmatrix.sync.aligned.m8n8.x4.trans.shared.b16 {%0,%1,%2,%3}, [%4];" \
        : "=r"((r)[0]), "=r"((r)[1]), "=r"((r)[2]), "=r"((r)[3]) : "r"(addr))

__device__ __forceinline__ void split2(float v, __nv_bfloat16& h, __nv_bfloat16& l) {
    h = __float2bfloat16(v);
    l = __float2bfloat16(v - __bfloat162float(h));
}
__device__ __forceinline__ uint32_t packbf(float a, float b) {
    __nv_bfloat162 t; t.x = __float2bfloat16(a); t.y = __float2bfloat16(b);
    return *(uint32_t*)&t;
}

// ---------------------------------------------------------------------------
// fp32 -> bf16 hi/lo split
// ---------------------------------------------------------------------------
__global__ __launch_bounds__(256) void split_kernel(
    const float* __restrict__ x, __nv_bfloat16* __restrict__ hi,
    __nv_bfloat16* __restrict__ lo, int n)
{
    int i = (blockIdx.x * 256 + threadIdx.x) * 4;
    if (i >= n) return;
    float4 v = *(const float4*)(x + i);
    __nv_bfloat16 h0, h1, h2, h3, l0, l1, l2, l3;
    split2(v.x, h0, l0); split2(v.y, h1, l1);
    split2(v.z, h2, l2); split2(v.w, h3, l3);
    __nv_bfloat162 hh0; hh0.x = h0; hh0.y = h1;
    __nv_bfloat162 hh1; hh1.x = h2; hh1.y = h3;
    __nv_bfloat162 ll0; ll0.x = l0; ll0.y = l1;
    __nv_bfloat162 ll1; ll1.x = l2; ll1.y = l3;
    *(__nv_bfloat162*)(hi + i)     = hh0;
    *(__nv_bfloat162*)(hi + i + 2) = hh1;
    *(__nv_bfloat162*)(lo + i)     = ll0;
    *(__nv_bfloat162*)(lo + i + 2) = ll1;
}

// ---------------------------------------------------------------------------
// mma.sync split-bf16 GEMM (NT). Single barrier per K-chunk (2-stage ring:
// top wait0+bar proves all warps left the buffer the next prefetch targets).
// ---------------------------------------------------------------------------
#define SA 40
#define TILE_H (128 * SA)
#define GEMM_SMEM (2 * 4 * TILE_H * 2)

template <int SPLIT_OUT>
__global__ __launch_bounds__(256, 2) void gemm_mma(
    const __nv_bfloat16* __restrict__ Ahi, const __nv_bfloat16* __restrict__ Alo,
    const __nv_bfloat16* __restrict__ Bhi, const __nv_bfloat16* __restrict__ Blo,
    const float* __restrict__ bias, float* __restrict__ C,
    __nv_bfloat16* __restrict__ Chi, __nv_bfloat16* __restrict__ Clo,
    int N, int K)
{
    extern __shared__ __nv_bfloat16 sh[];
    const uint32_t sbase = (uint32_t)__cvta_generic_to_shared(sh);
    const int tid = threadIdx.x;
    const int wid = tid >> 5, lane = tid & 31;
    const int warp_m = wid >> 2, warp_n = wid & 3;
    const int bm = blockIdx.y * 128, bn = blockIdx.x * 128;

    const int lrow = tid >> 1;
    const int lofs = (tid & 1) * 16;
    const __nv_bfloat16* srcs[4];
    srcs[0] = Ahi + (size_t)(bm + lrow) * K + lofs;
    srcs[1] = Alo + (size_t)(bm + lrow) * K + lofs;
    srcs[2] = Bhi + (size_t)(bn + lrow) * K + lofs;
    srcs[3] = Blo + (size_t)(bn + lrow) * K + lofs;
    const uint32_t sdst = sbase + (uint32_t)(lrow * SA + lofs) * 2;

    const uint32_t a_loff =
        (uint32_t)(((warp_m * 64 + (lane & 15)) * SA + (lane >> 4) * 8) * 2);
    const uint32_t b_loff =
        (uint32_t)(((warp_n * 32 + (lane & 7) + ((lane >> 4) & 1) * 8) * SA +
                    ((lane >> 3) & 1) * 8) * 2);

    const int nchunks = K >> 5;

#pragma unroll
    for (int tI = 0; tI < 4; tI++) {
        uint32_t d = sdst + tI * TILE_H * 2;
        cpa16(d, srcs[tI]);
        cpa16(d + 16, srcs[tI] + 8);
    }
    cpa_commit();

    float acc[4][4][4];
#pragma unroll
    for (int mi = 0; mi < 4; mi++)
#pragma unroll
        for (int ni = 0; ni < 4; ni++)
#pragma unroll
            for (int j = 0; j < 4; j++) acc[mi][ni][j] = 0.f;

    for (int c = 0; c < nchunks; ++c) {
        cpa_wait0();
        __syncthreads();

        if (c + 1 < nchunks) {
            const int s1 = (c + 1) & 1;
            const int ko = (c + 1) * 32;
#pragma unroll
            for (int tI = 0; tI < 4; tI++) {
                uint32_t d = sdst + (s1 * 4 + tI) * TILE_H * 2;
                cpa16(d, srcs[tI] + ko);
                cpa16(d + 16, srcs[tI] + ko + 8);
            }
            cpa_commit();
        }

        const uint32_t st   = sbase + (uint32_t)((c & 1) * 4) * TILE_H * 2;
        const uint32_t uAhi = st;
        const uint32_t uAlo = st + TILE_H * 2;
        const uint32_t uBhi = st + 2 * TILE_H * 2;
        const uint32_t uBlo = st + 3 * TILE_H * 2;

#pragma unroll
        for (int ks = 0; ks < 2; ++ks) {
            const uint32_t ko = ks * 32;
            uint32_t ahi[4][4], alo[4][4], bhi[4][2], blo[4][2];
#pragma unroll
            for (int mi = 0; mi < 4; mi++) {
                LDSM4(ahi[mi], uAhi + a_loff + mi * (16 * SA * 2) + ko);
                LDSM4(alo[mi], uAlo + a_loff + mi * (16 * SA * 2) + ko);
            }
#pragma unroll
            for (int np = 0; np < 2; np++) {
                uint32_t tb[4];
                LDSM4(tb, uBhi + b_loff + np * (16 * SA * 2) + ko);
                bhi[2 * np][0] = tb[0]; bhi[2 * np][1] = tb[1];
                bhi[2 * np + 1][0] = tb[2]; bhi[2 * np + 1][1] = tb[3];
                LDSM4(tb, uBlo + b_loff + np * (16 * SA * 2) + ko);
                blo[2 * np][0] = tb[0]; blo[2 * np][1] = tb[1];
                blo[2 * np + 1][0] = tb[2]; blo[2 * np + 1][1] = tb[3];
            }
#pragma unroll
            for (int mi = 0; mi < 4; mi++)
#pragma unroll
                for (int ni = 0; ni < 4; ni++) {
                    MMA16816(acc[mi][ni], ahi[mi], bhi[ni]);
                    MMA16816(acc[mi][ni], alo[mi], bhi[ni]);
                    MMA16816(acc[mi][ni], ahi[mi], blo[ni]);
                }
        }
        // single barrier per chunk: next iteration's top barrier protects reuse
    }

#pragma unroll
    for (int mi = 0; mi < 4; mi++) {
        int row = bm + warp_m * 64 + mi * 16 + (lane >> 2);
#pragma unroll
        for (int ni = 0; ni < 4; ni++) {
            int col = bn + warp_n * 32 + ni * 8 + (lane & 3) * 2;
            float b0 = bias[col], b1 = bias[col + 1];
            float o0 = acc[mi][ni][0] + b0, o1 = acc[mi][ni][1] + b1;
            float o2 = acc[mi][ni][2] + b0, o3 = acc[mi][ni][3] + b1;
            if (SPLIT_OUT) {
                __nv_bfloat16 h0, h1, l0, l1;
                split2(o0, h0, l0); split2(o1, h1, l1);
                __nv_bfloat162 ph; ph.x = h0; ph.y = h1;
                __nv_bfloat162 pl; pl.x = l0; pl.y = l1;
                *(__nv_bfloat162*)(Chi + (size_t)row * N + col) = ph;
                *(__nv_bfloat162*)(Clo + (size_t)row * N + col) = pl;
                split2(o2, h0, l0); split2(o3, h1, l1);
                ph.x = h0; ph.y = h1; pl.x = l0; pl.y = l1;
                *(__nv_bfloat162*)(Chi + (size_t)(row + 8) * N + col) = ph;
                *(__nv_bfloat162*)(Clo + (size_t)(row + 8) * N + col) = pl;
            } else {
                *(float2*)(C + (size_t)row * N + col) = make_float2(o0, o1);
                *(float2*)(C + (size_t)(row + 8) * N + col) = make_float2(o2, o3);
            }
        }
    }
}

// ---------------------------------------------------------------------------
// Tensor-core flash attention. K AND V both raw cp.async rows (double-
// buffered); V B-fragments via ldmatrix.x4.trans (no scalar transpose).
// One barrier per kt-tile. SMEM 108KB -> still 2 CTAs/SM.
// ---------------------------------------------------------------------------
#define QS 72
#define A_QH 0
#define A_QL (128 * QS)
#define A_KV0 (2 * 128 * QS)                // start of KV stages (halfs)
#define KV_T (64 * QS)                      // one 64x72 tile (halfs)
#define KV_STAGE (4 * KV_T)                 // KH,KL,VH,VL per stage
#define ATTN_SMEM ((A_KV0 + 2 * KV_STAGE) * 2)   // 110592 bytes

__global__ __launch_bounds__(256, 2) void attn_mma(
    const __nv_bfloat16* __restrict__ qkvh,
    const __nv_bfloat16* __restrict__ qkvl,
    __nv_bfloat16* __restrict__ chi, __nv_bfloat16* __restrict__ clo)
{
    extern __shared__ __nv_bfloat16 sh[];
    const uint32_t sbase = (uint32_t)__cvta_generic_to_shared(sh);
    const int tid = threadIdx.x;
    const int wid = tid >> 5, lane = tid & 31;
    const int q0 = blockIdx.x * 128;
    const int h  = blockIdx.y;
    const int t  = blockIdx.z;
    const size_t tbase = (size_t)t * B_DIM * D3 + h * HD_DIM;

    // KV prefetch addressing: thread covers one 16-half segment of each tile
    const int kr = tid >> 2, kc0 = (tid & 3) * 16;
    const uint32_t kvdst = (uint32_t)(kr * QS + kc0) * 2;

    // ---- preload Q (hi+lo) and KV stage 0 ----
    {
        const int r = tid >> 1, c0 = (tid & 1) * 32;
        const __nv_bfloat16* qh_src = qkvh + tbase + (size_t)(q0 + r) * D3 + c0;
        const __nv_bfloat16* ql_src = qkvl + tbase + (size_t)(q0 + r) * D3 + c0;
        const uint32_t dh = sbase + (uint32_t)(A_QH + r * QS + c0) * 2;
        const uint32_t dl = sbase + (uint32_t)(A_QL + r * QS + c0) * 2;
#pragma unroll
        for (int j = 0; j < 4; j++) {
            cpa16(dh + j * 16, qh_src + j * 8);
            cpa16(dl + j * 16, ql_src + j * 8);
        }
        const size_t rowb = tbase + (size_t)kr * D3;
        const uint32_t s0 = sbase + A_KV0 * 2;
        cpa16(s0 + kvdst,                 qkvh + rowb + D_DIM + kc0);
        cpa16(s0 + kvdst + 16,            qkvh + rowb + D_DIM + kc0 + 8);
        cpa16(s0 + KV_T * 2 + kvdst,      qkvl + rowb + D_DIM + kc0);
        cpa16(s0 + KV_T * 2 + kvdst + 16, qkvl + rowb + D_DIM + kc0 + 8);
        cpa16(s0 + 2 * KV_T * 2 + kvdst,      qkvh + rowb + 2 * D_DIM + kc0);
        cpa16(s0 + 2 * KV_T * 2 + kvdst + 16, qkvh + rowb + 2 * D_DIM + kc0 + 8);
        cpa16(s0 + 3 * KV_T * 2 + kvdst,      qkvl + rowb + 2 * D_DIM + kc0);
        cpa16(s0 + 3 * KV_T * 2 + kvdst + 16, qkvl + rowb + 2 * D_DIM + kc0 + 8);
        cpa_commit();
    }

    // ldmatrix lane offsets (bytes)
    const uint32_t q_loff =
        (uint32_t)(((wid * 16 + (lane & 15)) * QS + (lane >> 4) * 8) * 2);
    const uint32_t k_loff =
        (uint32_t)((((lane & 7) + ((lane >> 4) & 1) * 8) * QS +
                    ((lane >> 3) & 1) * 8) * 2);
    const uint32_t v_loff =                      // .trans: rows +8 on bit3, cols +8 on bit4
        (uint32_t)((((lane & 7) + ((lane >> 3) & 1) * 8) * QS +
                    ((lane >> 4) & 1) * 8) * 2);
    const uint32_t uQH = sbase + A_QH * 2, uQL = sbase + A_QL * 2;

    float m[2] = {-INFINITY, -INFINITY}, l[2] = {0.f, 0.f};
    float O[8][4];
#pragma unroll
    for (int dt = 0; dt < 8; dt++)
#pragma unroll
        for (int j = 0; j < 4; j++) O[dt][j] = 0.f;

    const int cA = (lane & 3) * 2;
    const int rA = lane >> 2;

    for (int kt = 0; kt < 8; ++kt) {
        cpa_wait0();
        __syncthreads();

        if (kt + 1 < 8) {
            const size_t rowb = tbase + (size_t)((kt + 1) * 64 + kr) * D3;
            const uint32_t s1 = sbase + (uint32_t)(A_KV0 + ((kt + 1) & 1) * KV_STAGE) * 2;
            cpa16(s1 + kvdst,                 qkvh + rowb + D_DIM + kc0);
            cpa16(s1 + kvdst + 16,            qkvh + rowb + D_DIM + kc0 + 8);
            cpa16(s1 + KV_T * 2 + kvdst,      qkvl + rowb + D_DIM + kc0);
            cpa16(s1 + KV_T * 2 + kvdst + 16, qkvl + rowb + D_DIM + kc0 + 8);
            cpa16(s1 + 2 * KV_T * 2 + kvdst,      qkvh + rowb + 2 * D_DIM + kc0);
            cpa16(s1 + 2 * KV_T * 2 + kvdst + 16, qkvh + rowb + 2 * D_DIM + kc0 + 8);
            cpa16(s1 + 3 * KV_T * 2 + kvdst,      qkvl + rowb + 2 * D_DIM + kc0);
            cpa16(s1 + 3 * KV_T * 2 + kvdst + 16, qkvl + rowb + 2 * D_DIM + kc0 + 8);
            cpa_commit();
        }

        const uint32_t stg = sbase + (uint32_t)(A_KV0 + (kt & 1) * KV_STAGE) * 2;
        const uint32_t uKH = stg;
        const uint32_t uKL = stg + KV_T * 2;
        const uint32_t uVH = stg + 2 * KV_T * 2;
        const uint32_t uVL = stg + 3 * KV_T * 2;

        // ---- S = Q K^T (3-pass split) ----
        float S[8][4];
#pragma unroll
        for (int nt = 0; nt < 8; nt++)
#pragma unroll
            for (int j = 0; j < 4; j++) S[nt][j] = 0.f;

#pragma unroll
        for (int kc = 0; kc < 4; ++kc) {
            const uint32_t ko = kc * 32;
            uint32_t qh[4], ql[4];
            LDSM4(qh, uQH + q_loff + ko);
            LDSM4(ql, uQL + q_loff + ko);
#pragma unroll
            for (int np = 0; np < 4; np++) {
                uint32_t th[4], tl[4];
                LDSM4(th, uKH + k_loff + np * (16 * QS * 2) + ko);
                LDSM4(tl, uKL + k_loff + np * (16 * QS * 2) + ko);
                uint32_t kh0[2] = {th[0], th[1]}, kh1[2] = {th[2], th[3]};
                uint32_t kl0[2] = {tl[0], tl[1]}, kl1[2] = {tl[2], tl[3]};
                MMA16816(S[2 * np], qh, kh0);
                MMA16816(S[2 * np], ql, kh0);
                MMA16816(S[2 * np], qh, kl0);
                MMA16816(S[2 * np + 1], qh, kh1);
                MMA16816(S[2 * np + 1], ql, kh1);
                MMA16816(S[2 * np + 1], qh, kl1);
            }
        }
#pragma unroll
        for (int nt = 0; nt < 8; nt++)
#pragma unroll
            for (int j = 0; j < 4; j++) S[nt][j] *= 0.125f;

        // ---- online softmax ----
        float sf[2];
#pragma unroll
        for (int rh = 0; rh < 2; rh++) {
            float mv = m[rh];
#pragma unroll
            for (int nt = 0; nt < 8; nt++)
                mv = fmaxf(mv, fmaxf(S[nt][2 * rh], S[nt][2 * rh + 1]));
            mv = fmaxf(mv, __shfl_xor_sync(0xffffffffu, mv, 1));
            mv = fmaxf(mv, __shfl_xor_sync(0xffffffffu, mv, 2));
            sf[rh] = __expf(m[rh] - mv);
            m[rh] = mv;
            float rs = 0.f;
#pragma unroll
            for (int nt = 0; nt < 8; nt++) {
                float p0 = __expf(S[nt][2 * rh] - mv);
                float p1 = __expf(S[nt][2 * rh + 1] - mv);
                S[nt][2 * rh] = p0; S[nt][2 * rh + 1] = p1;
                rs += p0 + p1;
            }
            rs += __shfl_xor_sync(0xffffffffu, rs, 1);
            rs += __shfl_xor_sync(0xffffffffu, rs, 2);
            l[rh] = l[rh] * sf[rh] + rs;
        }
#pragma unroll
        for (int dt = 0; dt < 8; dt++) {
            O[dt][0] *= sf[0]; O[dt][1] *= sf[0];
            O[dt][2] *= sf[1]; O[dt][3] *= sf[1];
        }

        // ---- O += P V (V frags via ldmatrix.trans on raw rows) ----
#pragma unroll
        for (int kc = 0; kc < 4; ++kc) {
            uint32_t ph[4], pl[4];
            {
                __nv_bfloat16 h0, h1, l0, l1;
                split2(S[2 * kc][0], h0, l0); split2(S[2 * kc][1], h1, l1);
                ph[0] = packbf(__bfloat162float(h0), __bfloat162float(h1));
                pl[0] = packbf(__bfloat162float(l0), __bfloat162float(l1));
                split2(S[2 * kc][2], h0, l0); split2(S[2 * kc][3], h1, l1);
                ph[1] = packbf(__bfloat162float(h0), __bfloat162float(h1));
                pl[1] = packbf(__bfloat162float(l0), __bfloat162float(l1));
                split2(S[2 * kc + 1][0], h0, l0); split2(S[2 * kc + 1][1], h1, l1);
                ph[2] = packbf(__bfloat162float(h0), __bfloat162float(h1));
                pl[2] = packbf(__bfloat162float(l0), __bfloat162float(l1));
                split2(S[2 * kc + 1][2], h0, l0); split2(S[2 * kc + 1][3], h1, l1);
                ph[3] = packbf(__bfloat162float(h0), __bfloat162float(h1));
                pl[3] = packbf(__bfloat162float(l0), __bfloat162float(l1));
            }
            const uint32_t kbase = kc * (16 * QS * 2);   // key-block rows
#pragma unroll
            for (int dp = 0; dp < 4; dp++) {
                uint32_t th[4], tl[4];
                LDSM4T(th, uVH + v_loff + kbase + dp * 32);
                LDSM4T(tl, uVL + v_loff + kbase + dp * 32);
                uint32_t vh0[2] = {th[0], th[1]}, vh1[2] = {th[2], th[3]};
                uint32_t vl0[2] = {tl[0], tl[1]}, vl1[2] = {tl[2], tl[3]};
                MMA16816(O[2 * dp], ph, vh0);
                MMA16816(O[2 * dp], pl, vh0);
                MMA16816(O[2 * dp], ph, vl0);
                MMA16816(O[2 * dp + 1], ph, vh1);
                MMA16816(O[2 * dp + 1], pl, vh1);
                MMA16816(O[2 * dp + 1], ph, vl1);
            }
        }
    }

    // ---- epilogue ----
    float inv0 = 1.f / l[0], inv1 = 1.f / l[1];
#pragma unroll
    for (int rh = 0; rh < 2; rh++) {
        const float inv = rh ? inv1 : inv0;
        const int row = q0 + wid * 16 + rA + rh * 8;
        const size_t rb = ((size_t)t * B_DIM + row) * D_DIM + h * HD_DIM;
#pragma unroll
        for (int dt = 0; dt < 8; dt++) {
            float o0 = O[dt][2 * rh] * inv, o1 = O[dt][2 * rh + 1] * inv;
            __nv_bfloat16 h0, h1, l0, l1;
            split2(o0, h0, l0); split2(o1, h1, l1);
            __nv_bfloat162 ph; ph.x = h0; ph.y = h1;
            __nv_bfloat162 pL; pL.x = l0; pL.y = l1;
            *(__nv_bfloat162*)(chi + rb + dt * 8 + cA) = ph;
            *(__nv_bfloat162*)(clo + rb + dt * 8 + cA) = pL;
        }
    }
}

// ---------------------------------------------------------------------------
// Stage 4
// ---------------------------------------------------------------------------
__global__ __launch_bounds__(256) void rownorm_kernel(
    const float* __restrict__ x, float* __restrict__ inv)
{
    int warp = threadIdx.x >> 5, lane = threadIdx.x & 31;
    int row = blockIdx.x * 8 + warp;
    const float* p = x + (size_t)row * D_DIM;
    float s = 0.f;
    for (int d = lane; d < D_DIM; d += 32) { float v = p[d]; s = fmaf(v, v, s); }
#pragma unroll
    for (int o = 16; o > 0; o >>= 1) s += __shfl_xor_sync(0xffffffffu, s, o);
    if (lane == 0) inv[row] = 1.f / fmaxf(sqrtf(s), 1e-8f);
}

__global__ __launch_bounds__(256) void mean_kernel(
    const float* __restrict__ x, const float* __restrict__ inv,
    float* __restrict__ mean)
{
    __shared__ float sinv[B_DIM];
    int t = blockIdx.x;
    int d = blockIdx.y * 256 + threadIdx.x;
    for (int i = threadIdx.x; i < B_DIM; i += 256) sinv[i] = inv[t * B_DIM + i];
    __syncthreads();
    const float* p = x + (size_t)t * B_DIM * D_DIM + d;
    float s = 0.f;
    for (int i = 0; i < B_DIM; i++) s = fmaf(p[(size_t)i * D_DIM], sinv[i], s);
    mean[t * D_DIM + d] = s * (1.f / B_DIM);
}

__global__ __launch_bounds__(256) void adj_kernel(
    const float* __restrict__ x, const float* __restrict__ inv,
    const float* __restrict__ mean, float* __restrict__ out)
{
    int warp = threadIdx.x >> 5, lane = threadIdx.x & 31;
    int row = blockIdx.x * 8 + warp;
    int t = row >> 9;
    const float* p = x + (size_t)row * D_DIM;
    const float* mp = mean + t * D_DIM;
    float s = 0.f;
    for (int d = lane; d < D_DIM; d += 32) s = fmaf(p[d], mp[d], s);
#pragma unroll
    for (int o = 16; o > 0; o >>= 1) s += __shfl_xor_sync(0xffffffffu, s, o);
    if (lane == 0) out[row] = s * inv[row];
}

// ---------------------------------------------------------------------------
extern "C" void kernel_launch(void* const* d_in, const int* in_sizes, int n_in,
                              void* d_out, int out_size)
{
    const float* node  = (const float*)d_in[0];
    const float* w_in  = (const float*)d_in[1];
    const float* b_in  = (const float*)d_in[2];
    const float* w_out = (const float*)d_in[3];
    const float* b_out = (const float*)d_in[4];
    float* out = (float*)d_out;

    float *o, *inv, *mean;
    __nv_bfloat16 *qkvh, *qkvl, *nhi, *nlo, *chi, *clo, *wihi, *wilo, *wohi, *wolo;
    cudaGetSymbolAddress((void**)&qkvh, g_qkvh);
    cudaGetSymbolAddress((void**)&qkvl, g_qkvl);
    cudaGetSymbolAddress((void**)&o,    g_out);
    cudaGetSymbolAddress((void**)&inv,  g_inv);
    cudaGetSymbolAddress((void**)&mean, g_mean);
    cudaGetSymbolAddress((void**)&nhi,  g_nhi);
    cudaGetSymbolAddress((void**)&nlo,  g_nlo);
    cudaGetSymbolAddress((void**)&chi,  g_chi);
    cudaGetSymbolAddress((void**)&clo,  g_clo);
    cudaGetSymbolAddress((void**)&wihi, g_wihi);
    cudaGetSymbolAddress((void**)&wilo, g_wilo);
    cudaGetSymbolAddress((void**)&wohi, g_wohi);
    cudaGetSymbolAddress((void**)&wolo, g_wolo);

    cudaFuncSetAttribute(gemm_mma<0>,
                         cudaFuncAttributeMaxDynamicSharedMemorySize, GEMM_SMEM);
    cudaFuncSetAttribute(gemm_mma<1>,
                         cudaFuncAttributeMaxDynamicSharedMemorySize, GEMM_SMEM);
    cudaFuncSetAttribute(attn_mma,
                         cudaFuncAttributeMaxDynamicSharedMemorySize, ATTN_SMEM);

    const int n_node = M_DIM * D_DIM;
    const int n_wi   = D3 * D_DIM;
    const int n_wo   = D_DIM * D_DIM;

    split_kernel<<<n_node / 1024, 256>>>(node, nhi, nlo, n_node);
    split_kernel<<<n_wi   / 1024, 256>>>(w_in, wihi, wilo, n_wi);
    split_kernel<<<n_wo   / 1024, 256>>>(w_out, wohi, wolo, n_wo);
    gemm_mma<1><<<dim3(D3 / 128, M_DIM / 128), 256, GEMM_SMEM>>>(
        nhi, nlo, wihi, wilo, b_in, nullptr, qkvh, qkvl, D3, D_DIM);
    attn_mma<<<dim3(B_DIM / 128, H_DIM, T_DIM), 256, ATTN_SMEM>>>(
        qkvh, qkvl, chi, clo);
    gemm_mma<0><<<dim3(D_DIM / 128, M_DIM / 128), 256, GEMM_SMEM>>>(
        chi, clo, wohi, wolo, b_out, o, nullptr, nullptr, D_DIM, D_DIM);
    rownorm_kernel<<<M_DIM / 8, 256>>>(o, inv);
    mean_kernel<<<dim3(T_DIM, D_DIM / 256), 256>>>(o, inv, mean);
    adj_kernel<<<M_DIM / 8, 256>>>(o, inv, mean, out);
}